// round 8
// baseline (speedup 1.0000x reference)
#include <cuda_runtime.h>
#include <cuda_bf16.h>
#include <math.h>
#include <stddef.h>

#define B_SZ    1024
#define T_ENC   128
#define N_INP   128
#define N_HID   256
#define T_DEC   24
#define DEC_STEPS 30

// ---------------- device scratch (no runtime alloc allowed) ----------------
__device__ float          g_xi   [(size_t)B_SZ * T_ENC * N_HID];   // 134 MB
__device__ float          g_mid  [(size_t)B_SZ * T_ENC * N_HID];   // 134 MB
__device__ __nv_bfloat16  g_uex  [(size_t)B_SZ * N_INP * N_HID];   //  67 MB
__device__ __nv_bfloat16  g_udmid[(size_t)B_SZ * T_ENC * N_HID];   //  67 MB
__device__ float g_h [B_SZ * N_HID];
__device__ float g_c [B_SZ * N_HID];
__device__ float g_hm[B_SZ * N_HID];
__device__ float g_cm[B_SZ * N_HID];
__device__ float g_hd[B_SZ * N_HID];
__device__ float g_cd[B_SZ * N_HID];
__device__ float g_q    [B_SZ * N_HID];
__device__ float g_xa   [B_SZ * N_INP];
__device__ float g_gates[B_SZ * 4 * N_HID];
__device__ float g_decin[B_SZ * N_HID];

// ---------------- helpers ----------------
__device__ __forceinline__ float tanhfast(float x) {
    float y; asm("tanh.approx.f32 %0, %1;" : "=f"(y) : "f"(x)); return y;
}
__device__ __forceinline__ float sigf(float x) {
    return 1.0f / (1.0f + expf(-x));
}

// ---------------- init: zero all recurrent state ----------------
__global__ void init_state_kernel() {
    int i = blockIdx.x * 256 + threadIdx.x;   // grid 1024 x 256 == B*N_HID
    g_h[i] = 0.f; g_c[i] = 0.f;
    g_hm[i] = 0.f; g_cm[i] = 0.f;
    g_hd[i] = 0.f; g_cd[i] = 0.f;
}

// ---------------- generic GEMM: Y = bias1+bias2+addin + A1*W1^T + A2*W2^T ----
// A: (M x K) row-major with stride lda.  W: (N x K) row-major with stride ldw.
// Requires M%64==0, N%64==0, K%16==0, lda%4==0, ldw%4==0 (all hold here).
__global__ void __launch_bounds__(256) gemm2_kernel(
    float* __restrict__ Yf, __nv_bfloat16* __restrict__ Yh,
    int M, int N,
    const float* __restrict__ A1, int lda1, const float* __restrict__ W1, int ldw1, int K1,
    const float* __restrict__ A2, int lda2, const float* __restrict__ W2, int ldw2, int K2,
    const float* __restrict__ bias1, const float* __restrict__ bias2,
    const float* __restrict__ addin, size_t ld_add)
{
    __shared__ float As[16][68];
    __shared__ float Ws[16][68];

    const int m0 = blockIdx.y * 64;
    const int n0 = blockIdx.x * 64;
    const int tid  = threadIdx.x;
    const int lrow = tid >> 2;           // 0..63
    const int lc4  = (tid & 3) * 4;      // 0,4,8,12
    const int tm0  = (tid >> 4) * 4;     // 0..60
    const int tn0  = (tid & 15) * 4;     // 0..60

    float acc[4][4] = {};

    #pragma unroll 1
    for (int seg = 0; seg < 2; seg++) {
        const float* A = seg ? A2 : A1;
        if (A == nullptr) continue;
        const float* W = seg ? W2 : W1;
        const int lda  = seg ? lda2 : lda1;
        const int ldw  = seg ? ldw2 : ldw1;
        const int K    = seg ? K2   : K1;

        const float* Arow = A + (size_t)(m0 + lrow) * lda + lc4;
        const float* Wrow = W + (size_t)(n0 + lrow) * ldw + lc4;

        #pragma unroll 1
        for (int k0 = 0; k0 < K; k0 += 16) {
            float4 av = *(const float4*)(Arow + k0);
            float4 wv = *(const float4*)(Wrow + k0);
            __syncthreads();
            As[lc4 + 0][lrow] = av.x; As[lc4 + 1][lrow] = av.y;
            As[lc4 + 2][lrow] = av.z; As[lc4 + 3][lrow] = av.w;
            Ws[lc4 + 0][lrow] = wv.x; Ws[lc4 + 1][lrow] = wv.y;
            Ws[lc4 + 2][lrow] = wv.z; Ws[lc4 + 3][lrow] = wv.w;
            __syncthreads();
            #pragma unroll
            for (int k = 0; k < 16; k++) {
                float4 a4 = *(const float4*)&As[k][tm0];
                float4 b4 = *(const float4*)&Ws[k][tn0];
                float am[4] = {a4.x, a4.y, a4.z, a4.w};
                float bn[4] = {b4.x, b4.y, b4.z, b4.w};
                #pragma unroll
                for (int i = 0; i < 4; i++)
                    #pragma unroll
                    for (int j = 0; j < 4; j++)
                        acc[i][j] += am[i] * bn[j];
            }
        }
    }

    float badd[4];
    #pragma unroll
    for (int j = 0; j < 4; j++) {
        float v = 0.f;
        if (bias1) v += bias1[n0 + tn0 + j];
        if (bias2) v += bias2[n0 + tn0 + j];
        badd[j] = v;
    }

    #pragma unroll
    for (int i = 0; i < 4; i++) {
        size_t m = (size_t)(m0 + tm0 + i);
        #pragma unroll
        for (int j = 0; j < 4; j++) {
            size_t n = (size_t)(n0 + tn0 + j);
            float v = acc[i][j] + badd[j];
            if (addin) v += addin[m * ld_add + n];
            if (Yf) Yf[m * (size_t)N + n] = v;
            else    Yh[m * (size_t)N + n] = __float2bfloat16(v);
        }
    }
}

// ---------------- P1: ue_x[b,j,k] = Ue_b[k] + sum_t inp[b,t,j]*UeW[k,t] ------
// grid (k-tiles=4, j-tiles=2, b=1024), 256 threads, 64x64 tile, K=128 (t dim)
__global__ void __launch_bounds__(256) uex_kernel(
    const float* __restrict__ inp, const float* __restrict__ UeW,
    const float* __restrict__ Ueb, __nv_bfloat16* __restrict__ uex)
{
    __shared__ float As[16][68];   // As[t][j]
    __shared__ float Ws[16][68];   // Ws[t][k]
    const int b  = blockIdx.z;
    const int j0 = blockIdx.y * 64;
    const int k0 = blockIdx.x * 64;
    const int tid  = threadIdx.x;
    const int lrow = tid >> 2;
    const int lc4  = (tid & 3) * 4;
    const int tm0  = (tid >> 4) * 4;    // j offset
    const int tn0  = (tid & 15) * 4;    // k offset
    const int jl   = tid & 63;
    const int tq   = tid >> 6;          // 0..3

    const float* ib = inp + (size_t)b * (T_ENC * N_INP);
    float acc[4][4] = {};

    #pragma unroll 1
    for (int t0 = 0; t0 < T_ENC; t0 += 16) {
        __syncthreads();
        #pragma unroll
        for (int p = 0; p < 4; p++) {
            int tt = tq + p * 4;
            As[tt][jl] = ib[(size_t)(t0 + tt) * N_INP + j0 + jl];
        }
        float4 wv = *(const float4*)(UeW + (size_t)(k0 + lrow) * T_ENC + t0 + lc4);
        Ws[lc4 + 0][lrow] = wv.x; Ws[lc4 + 1][lrow] = wv.y;
        Ws[lc4 + 2][lrow] = wv.z; Ws[lc4 + 3][lrow] = wv.w;
        __syncthreads();
        #pragma unroll
        for (int k = 0; k < 16; k++) {
            float4 a4 = *(const float4*)&As[k][tm0];
            float4 b4 = *(const float4*)&Ws[k][tn0];
            float am[4] = {a4.x, a4.y, a4.z, a4.w};
            float bn[4] = {b4.x, b4.y, b4.z, b4.w};
            #pragma unroll
            for (int i = 0; i < 4; i++)
                #pragma unroll
                for (int j = 0; j < 4; j++)
                    acc[i][j] += am[i] * bn[j];
        }
    }

    #pragma unroll
    for (int i = 0; i < 4; i++) {
        size_t row = (size_t)b * (N_INP * N_HID) + (size_t)(j0 + tm0 + i) * N_HID;
        #pragma unroll
        for (int j = 0; j < 4; j++) {
            float v = acc[i][j] + Ueb[k0 + tn0 + j];
            uex[row + k0 + tn0 + j] = __float2bfloat16(v);
        }
    }
}

// ---------------- encoder attention: score->softmax->xa ----------------
__global__ void __launch_bounds__(256) attn_enc_kernel(
    const float* __restrict__ q, const __nv_bfloat16* __restrict__ uex,
    const float* __restrict__ VeW, const float* __restrict__ VeB,
    const float* __restrict__ inp, int t, float* __restrict__ xa)
{
    const int b = blockIdx.x;
    const int tid = threadIdx.x;
    const int lane = tid & 31;
    const int w = tid >> 5;

    __shared__ float sq[256], sv[256], ssc[128], sred[256];
    sq[tid] = q[(size_t)b * N_HID + tid];
    sv[tid] = VeW[tid];
    __syncthreads();

    const __nv_bfloat16* ub = uex + (size_t)b * (N_INP * N_HID);
    const float veb = VeB[0];

    for (int j = w; j < N_INP; j += 8) {
        const __nv_bfloat162* up = (const __nv_bfloat162*)(ub + (size_t)j * N_HID);
        float s = 0.f;
        #pragma unroll
        for (int i = 0; i < 4; i++) {
            __nv_bfloat162 u2 = up[lane + 32 * i];
            int k = 64 * i + 2 * lane;
            s += sv[k]     * tanhfast(sq[k]     + __low2float(u2));
            s += sv[k + 1] * tanhfast(sq[k + 1] + __high2float(u2));
        }
        #pragma unroll
        for (int o = 16; o > 0; o >>= 1) s += __shfl_xor_sync(0xffffffffu, s, o);
        if (lane == 0) ssc[j] = s + veb;
    }
    __syncthreads();

    // softmax over 128
    float x = (tid < 128) ? ssc[tid] : -1e30f;
    sred[tid] = x; __syncthreads();
    #pragma unroll
    for (int o = 128; o > 0; o >>= 1) {
        if (tid < o) sred[tid] = fmaxf(sred[tid], sred[tid + o]);
        __syncthreads();
    }
    float mx = sred[0];
    __syncthreads();
    float e = (tid < 128) ? expf(x - mx) : 0.f;
    sred[tid] = e; __syncthreads();
    #pragma unroll
    for (int o = 128; o > 0; o >>= 1) {
        if (tid < o) sred[tid] += sred[tid + o];
        __syncthreads();
    }
    float inv = 1.0f / sred[0];
    if (tid < 128) {
        float xv = inp[((size_t)b * T_ENC + t) * N_INP + tid];
        xa[(size_t)b * N_INP + tid] = xv * e * inv;
    }
}

// ---------------- decoder attention: t scores + dec_in = sum_j t_j*mid[b,j,:] ---
__global__ void __launch_bounds__(256) attn_dec_kernel(
    const float* __restrict__ wd, const __nv_bfloat16* __restrict__ udmid,
    const float* __restrict__ VdW, const float* __restrict__ VdB,
    const float* __restrict__ mid, float* __restrict__ decin)
{
    const int b = blockIdx.x;
    const int tid = threadIdx.x;
    const int lane = tid & 31;
    const int w = tid >> 5;

    __shared__ float sq[256], sv[256], st[128];
    sq[tid] = wd[(size_t)b * N_HID + tid];
    sv[tid] = VdW[tid];
    __syncthreads();

    const __nv_bfloat16* ub = udmid + (size_t)b * (T_ENC * N_HID);
    const float vdb = VdB[0];

    for (int j = w; j < T_ENC; j += 8) {
        const __nv_bfloat162* up = (const __nv_bfloat162*)(ub + (size_t)j * N_HID);
        float s = 0.f;
        #pragma unroll
        for (int i = 0; i < 4; i++) {
            __nv_bfloat162 u2 = up[lane + 32 * i];
            int k = 64 * i + 2 * lane;
            s += sv[k]     * tanhfast(sq[k]     + __low2float(u2));
            s += sv[k + 1] * tanhfast(sq[k + 1] + __high2float(u2));
        }
        #pragma unroll
        for (int o = 16; o > 0; o >>= 1) s += __shfl_xor_sync(0xffffffffu, s, o);
        if (lane == 0) st[j] = s + vdb;
    }
    __syncthreads();

    // dec_in[h] = sum_j st[j] * mid[b, j, h]
    const float* mb = mid + (size_t)b * (T_ENC * N_HID) + tid;
    float acc = 0.f;
    #pragma unroll 8
    for (int j = 0; j < T_ENC; j++)
        acc += st[j] * mb[(size_t)j * N_HID];
    decin[(size_t)b * N_HID + tid] = acc;
}

// ---------------- LSTM cell (enc / mid): accurate activations ----------------
__global__ void __launch_bounds__(256) lstm_cell_kernel(
    const float* __restrict__ g, float* __restrict__ h, float* __restrict__ c,
    float* __restrict__ seq_out, int t)
{
    const int idx = blockIdx.x * 256 + threadIdx.x;    // B*N_HID
    const int b = idx >> 8;
    const int n = idx & 255;
    const float* gb = g + (size_t)b * (4 * N_HID);
    float gi = gb[n];
    float gf = gb[n + N_HID];
    float gg = gb[n + 2 * N_HID];
    float go = gb[n + 3 * N_HID];
    float c2 = sigf(gf) * c[idx] + sigf(gi) * tanhf(gg);
    float h2 = sigf(go) * tanhf(c2);
    c[idx] = c2;
    h[idx] = h2;
    if (seq_out) seq_out[((size_t)b * T_ENC + t) * N_HID + n] = h2;
}

// ---------------- decoder cell + regression output ----------------
__global__ void __launch_bounds__(256) dec_cell_out_kernel(
    const float* __restrict__ g, float* __restrict__ h, float* __restrict__ c,
    const float* __restrict__ regW, const float* __restrict__ regB,
    float* __restrict__ out, int step)
{
    const int b = blockIdx.x;
    const int n = threadIdx.x;
    const int idx = b * N_HID + n;
    const float* gb = g + (size_t)b * (4 * N_HID);
    float gi = gb[n];
    float gf = gb[n + N_HID];
    float gg = gb[n + 2 * N_HID];
    float go = gb[n + 3 * N_HID];
    float c2 = sigf(gf) * c[idx] + sigf(gi) * tanhf(gg);
    float h2 = sigf(go) * tanhf(c2);
    c[idx] = c2;
    h[idx] = h2;

    __shared__ float sr[256];
    sr[n] = regW[n] * h2;
    __syncthreads();
    #pragma unroll
    for (int o = 128; o > 0; o >>= 1) {
        if (n < o) sr[n] += sr[n + o];
        __syncthreads();
    }
    if (n == 0 && step >= DEC_STEPS - T_DEC)
        out[(size_t)b * T_DEC + (step - (DEC_STEPS - T_DEC))] = sr[0] + regB[0];
}

// ---------------- host launcher ----------------
extern "C" void kernel_launch(void* const* d_in, const int* in_sizes, int n_in,
                              void* d_out, int out_size)
{
    (void)in_sizes; (void)n_in; (void)out_size;
    const float* inp  = (const float*)d_in[0];
    const float* UeW  = (const float*)d_in[2];
    const float* Ueb  = (const float*)d_in[3];
    const float* Ue2W = (const float*)d_in[4];
    const float* Ue2b = (const float*)d_in[5];
    const float* WeW  = (const float*)d_in[6];
    const float* Web  = (const float*)d_in[7];
    const float* VeW  = (const float*)d_in[8];
    const float* Veb  = (const float*)d_in[9];
    const float* UdW  = (const float*)d_in[10];
    const float* Udb  = (const float*)d_in[11];
    const float* WdW  = (const float*)d_in[12];
    const float* Wdb  = (const float*)d_in[13];
    const float* VdW  = (const float*)d_in[14];
    const float* Vdb  = (const float*)d_in[15];
    const float* eWih = (const float*)d_in[16];
    const float* eWhh = (const float*)d_in[17];
    const float* ebih = (const float*)d_in[18];
    const float* ebhh = (const float*)d_in[19];
    const float* mWih = (const float*)d_in[20];
    const float* mWhh = (const float*)d_in[21];
    const float* mbih = (const float*)d_in[22];
    const float* mbhh = (const float*)d_in[23];
    const float* dWih = (const float*)d_in[24];
    const float* dWhh = (const float*)d_in[25];
    const float* dbih = (const float*)d_in[26];
    const float* dbhh = (const float*)d_in[27];
    const float* regW = (const float*)d_in[28];
    const float* regb = (const float*)d_in[29];
    float* out = (float*)d_out;

    float *xi, *mid, *h, *c, *hm, *cm, *hd, *cd, *q, *xa, *g, *decin;
    __nv_bfloat16 *uex, *udmid;
    cudaGetSymbolAddress((void**)&xi,    g_xi);
    cudaGetSymbolAddress((void**)&mid,   g_mid);
    cudaGetSymbolAddress((void**)&uex,   g_uex);
    cudaGetSymbolAddress((void**)&udmid, g_udmid);
    cudaGetSymbolAddress((void**)&h,     g_h);
    cudaGetSymbolAddress((void**)&c,     g_c);
    cudaGetSymbolAddress((void**)&hm,    g_hm);
    cudaGetSymbolAddress((void**)&cm,    g_cm);
    cudaGetSymbolAddress((void**)&hd,    g_hd);
    cudaGetSymbolAddress((void**)&cd,    g_cd);
    cudaGetSymbolAddress((void**)&q,     g_q);
    cudaGetSymbolAddress((void**)&xa,    g_xa);
    cudaGetSymbolAddress((void**)&g,     g_gates);
    cudaGetSymbolAddress((void**)&decin, g_decin);

    init_state_kernel<<<1024, 256>>>();

    // P1: ue_x (bf16)
    uex_kernel<<<dim3(4, 2, 1024), 256>>>(inp, UeW, Ueb, uex);

    // P2: xi_all = inputs @ Ue2W^T + b  (M = B*T = 131072)
    gemm2_kernel<<<dim3(4, 2048), 256>>>(
        xi, nullptr, B_SZ * T_ENC, N_HID,
        inp, N_INP, Ue2W, N_INP, N_INP,
        nullptr, 0, nullptr, 0, 0,
        Ue2b, nullptr, nullptr, 0);

    // -------- encoder + mid recurrence --------
    for (int t = 0; t < T_ENC; t++) {
        // q = We_b + [h|c] @ WeW^T + xi[:, t, :]
        gemm2_kernel<<<dim3(4, 16), 256>>>(
            q, nullptr, B_SZ, N_HID,
            h, N_HID, WeW, 2 * N_HID, N_HID,
            c, N_HID, WeW + N_HID, 2 * N_HID, N_HID,
            Web, nullptr, xi + (size_t)t * N_HID, (size_t)T_ENC * N_HID);

        attn_enc_kernel<<<B_SZ, 256>>>(q, uex, VeW, Veb, inp, t, xa);

        // enc gates = bih + bhh + xa @ Wih^T + h @ Whh^T
        gemm2_kernel<<<dim3(16, 16), 256>>>(
            g, nullptr, B_SZ, 4 * N_HID,
            xa, N_INP, eWih, N_INP, N_INP,
            h, N_HID, eWhh, N_HID, N_HID,
            ebih, ebhh, nullptr, 0);

        lstm_cell_kernel<<<1024, 256>>>(g, h, c, nullptr, 0);

        // mid gates = bih + bhh + h_enc @ Wih^T + hm @ Whh^T
        gemm2_kernel<<<dim3(16, 16), 256>>>(
            g, nullptr, B_SZ, 4 * N_HID,
            h, N_HID, mWih, N_HID, N_HID,
            hm, N_HID, mWhh, N_HID, N_HID,
            mbih, mbhh, nullptr, 0);

        lstm_cell_kernel<<<1024, 256>>>(g, hm, cm, mid, t);
    }

    // P3: ud_mid = mid @ UdW^T + b  (bf16 out)
    gemm2_kernel<<<dim3(4, 2048), 256>>>(
        nullptr, udmid, B_SZ * T_ENC, N_HID,
        mid, N_HID, UdW, N_HID, N_HID,
        nullptr, 0, nullptr, 0, 0,
        Udb, nullptr, nullptr, 0);

    // -------- decoder --------
    for (int s = 0; s < DEC_STEPS; s++) {
        // wd = Wd_b + [hd|cd] @ WdW^T  (reuse q buffer)
        gemm2_kernel<<<dim3(4, 16), 256>>>(
            q, nullptr, B_SZ, N_HID,
            hd, N_HID, WdW, 2 * N_HID, N_HID,
            cd, N_HID, WdW + N_HID, 2 * N_HID, N_HID,
            Wdb, nullptr, nullptr, 0);

        attn_dec_kernel<<<B_SZ, 256>>>(q, udmid, VdW, Vdb, mid, decin);

        gemm2_kernel<<<dim3(16, 16), 256>>>(
            g, nullptr, B_SZ, 4 * N_HID,
            decin, N_HID, dWih, N_HID, N_HID,
            hd, N_HID, dWhh, N_HID, N_HID,
            dbih, dbhh, nullptr, 0);

        dec_cell_out_kernel<<<B_SZ, 256>>>(g, hd, cd, regW, regb, out, s);
    }
}

// round 10
// speedup vs baseline: 1.0440x; 1.0440x over previous
#include <cuda_runtime.h>
#include <cuda_bf16.h>
#include <math.h>
#include <stdint.h>
#include <stddef.h>

#define B_SZ    1024
#define T_ENC   128
#define N_INP   128
#define N_HID   256
#define T_DEC   24
#define DEC_STEPS 30

typedef __nv_bfloat16 bf16;

// ===================== device buffers =====================
struct DB {
    float xi   [(size_t)B_SZ * T_ENC * N_HID];
    float mid  [(size_t)B_SZ * T_ENC * N_HID];
    bf16  mid_hi[(size_t)B_SZ * T_ENC * N_HID];
    bf16  mid_lo[(size_t)B_SZ * T_ENC * N_HID];
    bf16  uex  [(size_t)B_SZ * N_INP * N_HID];
    bf16  udmid[(size_t)B_SZ * T_ENC * N_HID];
    bf16  inp_hi[(size_t)B_SZ * T_ENC * N_INP];
    bf16  inp_lo[(size_t)B_SZ * T_ENC * N_INP];
    bf16  We_hi[256 * 512],  We_lo[256 * 512];
    bf16  Wd_hi[256 * 512],  Wd_lo[256 * 512];
    bf16  Ue2_hi[256 * 128], Ue2_lo[256 * 128];
    bf16  Ud_hi[256 * 256],  Ud_lo[256 * 256];
    bf16  Ge_hi[1024 * 384], Ge_lo[1024 * 384];
    bf16  Gm_hi[1024 * 512], Gm_lo[1024 * 512];
    bf16  Gd_hi[1024 * 512], Gd_lo[1024 * 512];
    float be[1024], bm[1024], bd[1024];
    float ce_f[B_SZ * N_HID], cm_f[B_SZ * N_HID], cd_f[B_SZ * N_HID];
    float hd_f[B_SZ * N_HID];
    float q[B_SZ * N_HID];
    bf16 he_hi[2][B_SZ * N_HID], he_lo[2][B_SZ * N_HID];
    bf16 ce_hi[2][B_SZ * N_HID], ce_lo[2][B_SZ * N_HID];
    bf16 hm_hi[2][B_SZ * N_HID], hm_lo[2][B_SZ * N_HID];
    bf16 hd_hi[2][B_SZ * N_HID], hd_lo[2][B_SZ * N_HID];
    bf16 cd_hi[2][B_SZ * N_HID], cd_lo[2][B_SZ * N_HID];
    bf16 xa_hi[B_SZ * N_INP], xa_lo[B_SZ * N_INP];
    bf16 di_hi[B_SZ * N_HID], di_lo[B_SZ * N_HID];
};
__device__ DB db;

// ===================== helpers =====================
__device__ __forceinline__ float tanhfast(float x) {
    float y; asm("tanh.approx.f32 %0, %1;" : "=f"(y) : "f"(x)); return y;
}
__device__ __forceinline__ float sigf(float x) { return 1.0f / (1.0f + expf(-x)); }
__device__ __forceinline__ void splitf(float v, bf16& hi, bf16& lo) {
    hi = __float2bfloat16(v);
    lo = __float2bfloat16(v - __bfloat162float(hi));
}
__device__ __forceinline__ uint32_t s2u(const void* p) {
    uint32_t a;
    asm("{ .reg .u64 t; cvta.to.shared.u64 t, %1; cvt.u32.u64 %0, t; }" : "=r"(a) : "l"(p));
    return a;
}
__device__ __forceinline__ void cp16(uint32_t saddr, const void* g) {
    asm volatile("cp.async.cg.shared.global [%0], [%1], 16;" :: "r"(saddr), "l"(g));
}
__device__ __forceinline__ void mma16816(float* d, uint32_t a0, uint32_t a1,
                                         uint32_t a2, uint32_t a3,
                                         uint32_t b0, uint32_t b1) {
    asm volatile("mma.sync.aligned.m16n8k16.row.col.f32.bf16.bf16.f32 "
        "{%0,%1,%2,%3}, {%4,%5,%6,%7}, {%8,%9}, {%0,%1,%2,%3};"
        : "+f"(d[0]), "+f"(d[1]), "+f"(d[2]), "+f"(d[3])
        : "r"(a0), "r"(a1), "r"(a2), "r"(a3), "r"(b0), "r"(b1));
}

// smem: 2 stages x [A_hi | A_lo | W_hi | W_lo], each 128 rows x 144B (72 bf16, 64 used)
#define ARR_BYTES   18432              // 128*144
#define STAGE_BYTES 73728              // 4*ARR_BYTES
#define STAGE_WORDS 18432              // /4
#define ARR_WORDS   4608
#define SMEM_BYTES  147456             // 2 stages

// ===================== HMMA GEMM + fused epilogues =====================
// Y[M,N] = A[M,K]*W[N,K]^T (A = concat(A1,A2) on K), bf16 hi/lo splits.
// npass: 1 = Ah*Wh only;  3 = Ah*Wh + Al*Wh + Ah*Wl (~fp32)
// mode 0: outf = D+bias(+addin); mode 1: outh = bf16(D+bias)
// mode 2: LSTM cell (N gate-interleaved n=4h+g): update cst, export h/c
__global__ void __launch_bounds__(256, 1) mma_gemm(
    int mode, int npass, int Ktot, int K1,
    const bf16* __restrict__ A1h, const bf16* __restrict__ A1l, int ld1,
    const bf16* __restrict__ A2h, const bf16* __restrict__ A2l, int ld2,
    const bf16* __restrict__ Wh,  const bf16* __restrict__ Wl,  int ldw,
    const float* __restrict__ bias,
    float* __restrict__ outf, bf16* __restrict__ outh, int ldo,
    const float* __restrict__ addin, size_t add_ld,
    float* __restrict__ cst,
    bf16* __restrict__ h_hi, bf16* __restrict__ h_lo,
    bf16* __restrict__ h2_hi, bf16* __restrict__ h2_lo, size_t h2ld,
    float* __restrict__ hf, size_t hfld,
    bf16* __restrict__ c_hi, bf16* __restrict__ c_lo)
{
    extern __shared__ char smem[];
    const uint32_t sb = s2u(smem);
    const uint32_t* sw = (const uint32_t*)smem;

    const int tid = threadIdx.x;
    const int m0 = blockIdx.y * 128;
    const int n0 = blockIdx.x * 128;
    const int w  = tid >> 5;
    const int wm = w >> 2;            // 0..1 (64-row half)
    const int wn = w & 3;             // 0..3 (32-col quarter)
    const int lane = tid & 31;
    const int qr = lane >> 2;         // 0..7
    const int qc = lane & 3;          // 0..3

    const int g2 = tid >> 7;          // 0: A loader, 1: W loader
    const int r  = tid & 127;
    const int NC = Ktot >> 6;

    // ---- chunk loader via cp.async ----
    auto load_chunk = [&](int ch, int stage) {
        const int k0 = ch << 6;
        const bf16 *ph, *pl; int ld, kk; size_t row;
        if (g2 == 0) {
            if (k0 < K1) { ph = A1h; pl = A1l; ld = ld1; kk = k0; }
            else         { ph = A2h; pl = A2l; ld = ld2; kk = k0 - K1; }
            row = (size_t)(m0 + r);
        } else {
            ph = Wh; pl = Wl; ld = ldw; kk = k0; row = (size_t)(n0 + r);
        }
        const char* gh = (const char*)(ph + row * ld + kk);
        uint32_t dst = sb + stage * STAGE_BYTES + g2 * 2 * ARR_BYTES + r * 144;
        #pragma unroll
        for (int i = 0; i < 8; i++) cp16(dst + i * 16, gh + i * 16);
        if (npass == 3) {
            const char* gl = (const char*)(pl + row * ld + kk);
            #pragma unroll
            for (int i = 0; i < 8; i++) cp16(dst + ARR_BYTES + i * 16, gl + i * 16);
        }
    };

    float acc[4][4][4] = {};

    load_chunk(0, 0);
    asm volatile("cp.async.commit_group;");

    for (int ch = 0; ch < NC; ch++) {
        const int stage = ch & 1;
        if (ch + 1 < NC) {
            load_chunk(ch + 1, stage ^ 1);
            asm volatile("cp.async.commit_group;");
            asm volatile("cp.async.wait_group 1;");
        } else {
            asm volatile("cp.async.wait_group 0;");
        }
        __syncthreads();

        const uint32_t* S = sw + stage * STAGE_WORDS;
        #pragma unroll
        for (int kk = 0; kk < 4; kk++) {
            const int pa = kk * 8 + qc;
            uint32_t bh[4][2], bl[4][2];
            #pragma unroll
            for (int nt = 0; nt < 4; nt++) {
                const int rB = (wn * 32 + nt * 8 + qr) * 36;
                bh[nt][0] = S[2 * ARR_WORDS + rB + pa];
                bh[nt][1] = S[2 * ARR_WORDS + rB + pa + 4];
                if (npass == 3) {
                    bl[nt][0] = S[3 * ARR_WORDS + rB + pa];
                    bl[nt][1] = S[3 * ARR_WORDS + rB + pa + 4];
                }
            }
            #pragma unroll
            for (int mt = 0; mt < 4; mt++) {
                const int rA  = (wm * 64 + mt * 16 + qr) * 36;
                const int rA8 = rA + 8 * 36;
                uint32_t ah0 = S[rA + pa],     ah1 = S[rA8 + pa];
                uint32_t ah2 = S[rA + pa + 4], ah3 = S[rA8 + pa + 4];
                #pragma unroll
                for (int nt = 0; nt < 4; nt++)
                    mma16816(acc[mt][nt], ah0, ah1, ah2, ah3, bh[nt][0], bh[nt][1]);
                if (npass == 3) {
                    uint32_t al0 = S[ARR_WORDS + rA + pa],     al1 = S[ARR_WORDS + rA8 + pa];
                    uint32_t al2 = S[ARR_WORDS + rA + pa + 4], al3 = S[ARR_WORDS + rA8 + pa + 4];
                    #pragma unroll
                    for (int nt = 0; nt < 4; nt++)
                        mma16816(acc[mt][nt], al0, al1, al2, al3, bh[nt][0], bh[nt][1]);
                    #pragma unroll
                    for (int nt = 0; nt < 4; nt++)
                        mma16816(acc[mt][nt], ah0, ah1, ah2, ah3, bl[nt][0], bl[nt][1]);
                }
            }
        }
        __syncthreads();
    }

    // ===================== epilogue =====================
    if (mode == 2) {
        #pragma unroll
        for (int mt = 0; mt < 4; mt++) {
            #pragma unroll
            for (int nt = 0; nt < 4; nt++) {
                float* d = acc[mt][nt];
                float p0 = __shfl_xor_sync(0xffffffffu, d[0], 1);
                float p1 = __shfl_xor_sync(0xffffffffu, d[1], 1);
                float p2 = __shfl_xor_sync(0xffffffffu, d[2], 1);
                float p3 = __shfl_xor_sync(0xffffffffu, d[3], 1);
                const int nbase = n0 + wn * 32 + nt * 8;
                const int hglob = (nbase >> 2) + (qc >> 1);
                const int nb4   = nbase + (qc >> 1) * 4;
                int row; float g0, g1, g2v, g3v;
                if ((qc & 1) == 0) {
                    row = m0 + wm * 64 + mt * 16 + qr;
                    g0 = d[0]; g1 = d[1]; g2v = p0; g3v = p1;
                } else {
                    row = m0 + wm * 64 + mt * 16 + qr + 8;
                    g0 = p2; g1 = p3; g2v = d[2]; g3v = d[3];
                }
                float gi = g0  + bias[nb4 + 0];
                float gf = g1  + bias[nb4 + 1];
                float gg = g2v + bias[nb4 + 2];
                float go = g3v + bias[nb4 + 3];
                const size_t off = (size_t)row * N_HID + hglob;
                float c2 = sigf(gf) * cst[off] + sigf(gi) * tanhf(gg);
                float h2 = sigf(go) * tanhf(c2);
                cst[off] = c2;
                bf16 hh, hl; splitf(h2, hh, hl);
                h_hi[off] = hh; h_lo[off] = hl;
                if (h2_hi) {
                    size_t o2 = (size_t)row * h2ld + hglob;
                    h2_hi[o2] = hh; h2_lo[o2] = hl;
                }
                if (hf) hf[(size_t)row * hfld + hglob] = h2;
                if (c_hi) {
                    bf16 ch_, cl_; splitf(c2, ch_, cl_);
                    c_hi[off] = ch_; c_lo[off] = cl_;
                }
            }
        }
    } else {
        #pragma unroll
        for (int mt = 0; mt < 4; mt++) {
            #pragma unroll
            for (int nt = 0; nt < 4; nt++) {
                float* d = acc[mt][nt];
                const size_t mr = (size_t)(m0 + wm * 64 + mt * 16 + qr);
                const int nc = n0 + wn * 32 + nt * 8 + qc * 2;
                float b0 = bias[nc], b1 = bias[nc + 1];
                float v00 = d[0] + b0, v01 = d[1] + b1;
                float v10 = d[2] + b0, v11 = d[3] + b1;
                if (addin) {
                    v00 += addin[mr * add_ld + nc];
                    v01 += addin[mr * add_ld + nc + 1];
                    v10 += addin[(mr + 8) * add_ld + nc];
                    v11 += addin[(mr + 8) * add_ld + nc + 1];
                }
                if (mode == 0) {
                    outf[mr * ldo + nc] = v00;       outf[mr * ldo + nc + 1] = v01;
                    outf[(mr + 8) * ldo + nc] = v10; outf[(mr + 8) * ldo + nc + 1] = v11;
                } else {
                    outh[mr * ldo + nc] = __float2bfloat16(v00);
                    outh[mr * ldo + nc + 1] = __float2bfloat16(v01);
                    outh[(mr + 8) * ldo + nc] = __float2bfloat16(v10);
                    outh[(mr + 8) * ldo + nc + 1] = __float2bfloat16(v11);
                }
            }
        }
    }
}

// ===================== prep kernels =====================
__global__ void init_state_kernel() {
    int i = blockIdx.x * 256 + threadIdx.x;
    bf16 z = __float2bfloat16(0.f);
    db.ce_f[i] = 0.f; db.cm_f[i] = 0.f; db.cd_f[i] = 0.f;
    db.he_hi[0][i] = z; db.he_lo[0][i] = z;
    db.ce_hi[0][i] = z; db.ce_lo[0][i] = z;
    db.hm_hi[0][i] = z; db.hm_lo[0][i] = z;
    db.hd_hi[0][i] = z; db.hd_lo[0][i] = z;
    db.cd_hi[0][i] = z; db.cd_lo[0][i] = z;
}

__global__ void split_arr(const float* __restrict__ src, bf16* __restrict__ hi,
                          bf16* __restrict__ lo, int n) {
    int i = blockIdx.x * 256 + threadIdx.x;
    if (i >= n) return;
    splitf(src[i], hi[i], lo[i]);
}

__global__ void gates_prep(const float* __restrict__ Wih, int Ki,
                           const float* __restrict__ Whh,
                           const float* __restrict__ bih, const float* __restrict__ bhh,
                           bf16* __restrict__ Whi, bf16* __restrict__ Wlo,
                           float* __restrict__ br, int Kt)
{
    int idx = blockIdx.x * 256 + threadIdx.x;
    if (idx >= 1024 * Kt) return;
    int nrow = idx / Kt, k = idx - nrow * Kt;
    int h = nrow >> 2, g = nrow & 3;
    float v = (k < Ki) ? Wih[(size_t)(g * 256 + h) * Ki + k]
                       : Whh[(size_t)(g * 256 + h) * 256 + (k - Ki)];
    splitf(v, Whi[idx], Wlo[idx]);
    if (k == 0) br[nrow] = bih[g * 256 + h] + bhh[g * 256 + h];
}

// ===================== ue_x (SIMT, bf16 out) =====================
__global__ void __launch_bounds__(256) uex_kernel(
    const float* __restrict__ inp, const float* __restrict__ UeW,
    const float* __restrict__ Ueb)
{
    __shared__ float As[16][68];
    __shared__ float Ws[16][68];
    const int b  = blockIdx.z;
    const int j0 = blockIdx.y * 64;
    const int k0 = blockIdx.x * 64;
    const int tid  = threadIdx.x;
    const int lrow = tid >> 2;
    const int lc4  = (tid & 3) * 4;
    const int tm0  = (tid >> 4) * 4;
    const int tn0  = (tid & 15) * 4;
    const int jl   = tid & 63;
    const int tq   = tid >> 6;

    const float* ib = inp + (size_t)b * (T_ENC * N_INP);
    float acc[4][4] = {};

    #pragma unroll 1
    for (int t0 = 0; t0 < T_ENC; t0 += 16) {
        __syncthreads();
        #pragma unroll
        for (int p = 0; p < 4; p++) {
            int tt = tq + p * 4;
            As[tt][jl] = ib[(size_t)(t0 + tt) * N_INP + j0 + jl];
        }
        float4 wv = *(const float4*)(UeW + (size_t)(k0 + lrow) * T_ENC + t0 + lc4);
        Ws[lc4 + 0][lrow] = wv.x; Ws[lc4 + 1][lrow] = wv.y;
        Ws[lc4 + 2][lrow] = wv.z; Ws[lc4 + 3][lrow] = wv.w;
        __syncthreads();
        #pragma unroll
        for (int k = 0; k < 16; k++) {
            float4 a4 = *(const float4*)&As[k][tm0];
            float4 b4 = *(const float4*)&Ws[k][tn0];
            float am[4] = {a4.x, a4.y, a4.z, a4.w};
            float bn[4] = {b4.x, b4.y, b4.z, b4.w};
            #pragma unroll
            for (int i = 0; i < 4; i++)
                #pragma unroll
                for (int j = 0; j < 4; j++)
                    acc[i][j] += am[i] * bn[j];
        }
    }
    #pragma unroll
    for (int i = 0; i < 4; i++) {
        size_t row = (size_t)b * (N_INP * N_HID) + (size_t)(j0 + tm0 + i) * N_HID;
        #pragma unroll
        for (int j = 0; j < 4; j++)
            db.uex[row + k0 + tn0 + j] = __float2bfloat16(acc[i][j] + Ueb[k0 + tn0 + j]);
    }
}

// ===================== attention kernels =====================
__global__ void __launch_bounds__(256) attn_enc_kernel(
    const float* __restrict__ inp, const float* __restrict__ VeW,
    const float* __restrict__ VeB, int t)
{
    const int b = blockIdx.x;
    const int tid = threadIdx.x;
    const int lane = tid & 31;
    const int w = tid >> 5;

    __shared__ float sq[256], sv[256], ssc[128], sred[256];
    sq[tid] = db.q[(size_t)b * N_HID + tid];
    sv[tid] = VeW[tid];
    __syncthreads();

    const bf16* ub = db.uex + (size_t)b * (N_INP * N_HID);
    const float veb = VeB[0];

    for (int j = w; j < N_INP; j += 8) {
        const __nv_bfloat162* up = (const __nv_bfloat162*)(ub + (size_t)j * N_HID);
        float s = 0.f;
        #pragma unroll
        for (int i = 0; i < 4; i++) {
            __nv_bfloat162 u2 = up[lane + 32 * i];
            int k = 64 * i + 2 * lane;
            s += sv[k]     * tanhfast(sq[k]     + __low2float(u2));
            s += sv[k + 1] * tanhfast(sq[k + 1] + __high2float(u2));
        }
        #pragma unroll
        for (int o = 16; o > 0; o >>= 1) s += __shfl_xor_sync(0xffffffffu, s, o);
        if (lane == 0) ssc[j] = s + veb;
    }
    __syncthreads();

    float x = (tid < 128) ? ssc[tid] : -1e30f;
    sred[tid] = x; __syncthreads();
    #pragma unroll
    for (int o = 128; o > 0; o >>= 1) {
        if (tid < o) sred[tid] = fmaxf(sred[tid], sred[tid + o]);
        __syncthreads();
    }
    float mx = sred[0];
    __syncthreads();
    float e = (tid < 128) ? expf(x - mx) : 0.f;
    sred[tid] = e; __syncthreads();
    #pragma unroll
    for (int o = 128; o > 0; o >>= 1) {
        if (tid < o) sred[tid] += sred[tid + o];
        __syncthreads();
    }
    float inv = 1.0f / sred[0];
    if (tid < 128) {
        float xv = inp[((size_t)b * T_ENC + t) * N_INP + tid];
        bf16 hh, hl; splitf(xv * e * inv, hh, hl);
        db.xa_hi[(size_t)b * N_INP + tid] = hh;
        db.xa_lo[(size_t)b * N_INP + tid] = hl;
    }
}

__global__ void __launch_bounds__(256) attn_dec_kernel(
    const float* __restrict__ VdW, const float* __restrict__ VdB)
{
    const int b = blockIdx.x;
    const int tid = threadIdx.x;
    const int lane = tid & 31;
    const int w = tid >> 5;

    __shared__ float sq[256], sv[256], st[128];
    sq[tid] = db.q[(size_t)b * N_HID + tid];
    sv[tid] = VdW[tid];
    __syncthreads();

    const bf16* ub = db.udmid + (size_t)b * (T_ENC * N_HID);
    const float vdb = VdB[0];

    for (int j = w; j < T_ENC; j += 8) {
        const __nv_bfloat162* up = (const __nv_bfloat162*)(ub + (size_t)j * N_HID);
        float s = 0.f;
        #pragma unroll
        for (int i = 0; i < 4; i++) {
            __nv_bfloat162 u2 = up[lane + 32 * i];
            int k = 64 * i + 2 * lane;
            s += sv[k]     * tanhfast(sq[k]     + __low2float(u2));
            s += sv[k + 1] * tanhfast(sq[k + 1] + __high2float(u2));
        }
        #pragma unroll
        for (int o = 16; o > 0; o >>= 1) s += __shfl_xor_sync(0xffffffffu, s, o);
        if (lane == 0) st[j] = s + vdb;
    }
    __syncthreads();

    const float* mb = db.mid + (size_t)b * (T_ENC * N_HID) + tid;
    float acc = 0.f;
    #pragma unroll 8
    for (int j = 0; j < T_ENC; j++)
        acc += st[j] * mb[(size_t)j * N_HID];
    bf16 hh, hl; splitf(acc, hh, hl);
    db.di_hi[(size_t)b * N_HID + tid] = hh;
    db.di_lo[(size_t)b * N_HID + tid] = hl;
}

// ===================== regression output =====================
__global__ void __launch_bounds__(256) reg_kernel(
    const float* __restrict__ regW, const float* __restrict__ regB,
    float* __restrict__ out, int col)
{
    const int b = blockIdx.x;
    const int n = threadIdx.x;
    __shared__ float sr[256];
    sr[n] = regW[n] * db.hd_f[(size_t)b * N_HID + n];
    __syncthreads();
    #pragma unroll
    for (int o = 128; o > 0; o >>= 1) {
        if (n < o) sr[n] += sr[n + o];
        __syncthreads();
    }
    if (n == 0) out[(size_t)b * T_DEC + col] = sr[0] + regB[0];
}

// ===================== host launcher =====================
extern "C" void kernel_launch(void* const* d_in, const int* in_sizes, int n_in,
                              void* d_out, int out_size)
{
    (void)in_sizes; (void)n_in; (void)out_size;
    const float* inp  = (const float*)d_in[0];
    const float* UeW  = (const float*)d_in[2];
    const float* Ueb  = (const float*)d_in[3];
    const float* Ue2W = (const float*)d_in[4];
    const float* Ue2b = (const float*)d_in[5];
    const float* WeW  = (const float*)d_in[6];
    const float* Web  = (const float*)d_in[7];
    const float* VeW  = (const float*)d_in[8];
    const float* Veb  = (const float*)d_in[9];
    const float* UdW  = (const float*)d_in[10];
    const float* Udb  = (const float*)d_in[11];
    const float* WdW  = (const float*)d_in[12];
    const float* Wdb  = (const float*)d_in[13];
    const float* VdW  = (const float*)d_in[14];
    const float* Vdb  = (const float*)d_in[15];
    const float* eWih = (const float*)d_in[16];
    const float* eWhh = (const float*)d_in[17];
    const float* ebih = (const float*)d_in[18];
    const float* ebhh = (const float*)d_in[19];
    const float* mWih = (const float*)d_in[20];
    const float* mWhh = (const float*)d_in[21];
    const float* mbih = (const float*)d_in[22];
    const float* mbhh = (const float*)d_in[23];
    const float* dWih = (const float*)d_in[24];
    const float* dWhh = (const float*)d_in[25];
    const float* dbih = (const float*)d_in[26];
    const float* dbhh = (const float*)d_in[27];
    const float* regW = (const float*)d_in[28];
    const float* regb = (const float*)d_in[29];
    float* out = (float*)d_out;

    cudaFuncSetAttribute(mma_gemm, cudaFuncAttributeMaxDynamicSharedMemorySize, SMEM_BYTES);

    DB* p;
    cudaGetSymbolAddress((void**)&p, db);

    init_state_kernel<<<1024, 256>>>();

    split_arr<<<(B_SZ * T_ENC * N_INP + 255) / 256, 256>>>(inp, p->inp_hi, p->inp_lo, B_SZ * T_ENC * N_INP);
    split_arr<<<(256 * 512 + 255) / 256, 256>>>(WeW,  p->We_hi,  p->We_lo,  256 * 512);
    split_arr<<<(256 * 512 + 255) / 256, 256>>>(WdW,  p->Wd_hi,  p->Wd_lo,  256 * 512);
    split_arr<<<(256 * 128 + 255) / 256, 256>>>(Ue2W, p->Ue2_hi, p->Ue2_lo, 256 * 128);
    split_arr<<<(256 * 256 + 255) / 256, 256>>>(UdW,  p->Ud_hi,  p->Ud_lo,  256 * 256);
    gates_prep<<<(1024 * 384 + 255) / 256, 256>>>(eWih, 128, eWhh, ebih, ebhh, p->Ge_hi, p->Ge_lo, p->be, 384);
    gates_prep<<<(1024 * 512 + 255) / 256, 256>>>(mWih, 256, mWhh, mbih, mbhh, p->Gm_hi, p->Gm_lo, p->bm, 512);
    gates_prep<<<(1024 * 512 + 255) / 256, 256>>>(dWih, 256, dWhh, dbih, dbhh, p->Gd_hi, p->Gd_lo, p->bd, 512);

    uex_kernel<<<dim3(4, 2, 1024), 256>>>(inp, UeW, Ueb);

    // xi = inp @ Ue2^T + b  (1-pass)
    mma_gemm<<<dim3(2, 1024), 256, SMEM_BYTES>>>(
        0, 1, 128, 128,
        p->inp_hi, p->inp_lo, 128, nullptr, nullptr, 0,
        p->Ue2_hi, p->Ue2_lo, 128, Ue2b,
        p->xi, nullptr, N_HID, nullptr, 0,
        nullptr, nullptr, nullptr, nullptr, nullptr, 0, nullptr, 0, nullptr, nullptr);

    // -------- encoder + mid recurrence --------
    for (int t = 0; t < T_ENC; t++) {
        int rp = t & 1, wp = rp ^ 1;
        // q = Web + [h|c] @ We^T + xi[:,t,:]   (1-pass)
        mma_gemm<<<dim3(2, 8), 256, SMEM_BYTES>>>(
            0, 1, 512, 256,
            p->he_hi[rp], p->he_lo[rp], 256, p->ce_hi[rp], p->ce_lo[rp], 256,
            p->We_hi, p->We_lo, 512, Web,
            p->q, nullptr, N_HID, p->xi + (size_t)t * N_HID, (size_t)T_ENC * N_HID,
            nullptr, nullptr, nullptr, nullptr, nullptr, 0, nullptr, 0, nullptr, nullptr);

        attn_enc_kernel<<<B_SZ, 256>>>(inp, VeW, Veb, t);

        // enc gates + cell (3-pass)
        mma_gemm<<<dim3(8, 8), 256, SMEM_BYTES>>>(
            2, 3, 384, 128,
            p->xa_hi, p->xa_lo, 128, p->he_hi[rp], p->he_lo[rp], 256,
            p->Ge_hi, p->Ge_lo, 384, p->be,
            nullptr, nullptr, 0, nullptr, 0,
            p->ce_f, p->he_hi[wp], p->he_lo[wp],
            nullptr, nullptr, 0, nullptr, 0,
            p->ce_hi[wp], p->ce_lo[wp]);

        // mid gates + cell (3-pass), exports mid[t] fp32 + hi/lo
        mma_gemm<<<dim3(8, 8), 256, SMEM_BYTES>>>(
            2, 3, 512, 256,
            p->he_hi[wp], p->he_lo[wp], 256, p->hm_hi[rp], p->hm_lo[rp], 256,
            p->Gm_hi, p->Gm_lo, 512, p->bm,
            nullptr, nullptr, 0, nullptr, 0,
            p->cm_f, p->hm_hi[wp], p->hm_lo[wp],
            p->mid_hi + (size_t)t * N_HID, p->mid_lo + (size_t)t * N_HID, (size_t)T_ENC * N_HID,
            p->mid + (size_t)t * N_HID, (size_t)T_ENC * N_HID,
            nullptr, nullptr);
    }

    // ud_mid = mid @ Ud^T + b  (1-pass, bf16 out)
    mma_gemm<<<dim3(2, 1024), 256, SMEM_BYTES>>>(
        1, 1, 256, 256,
        p->mid_hi, p->mid_lo, 256, nullptr, nullptr, 0,
        p->Ud_hi, p->Ud_lo, 256, Udb,
        nullptr, p->udmid, N_HID, nullptr, 0,
        nullptr, nullptr, nullptr, nullptr, nullptr, 0, nullptr, 0, nullptr, nullptr);

    // -------- decoder --------
    for (int s = 0; s < DEC_STEPS; s++) {
        int rp = s & 1, wp = rp ^ 1;
        // wd = Wdb + [hd|cd] @ Wd^T  (1-pass)
        mma_gemm<<<dim3(2, 8), 256, SMEM_BYTES>>>(
            0, 1, 512, 256,
            p->hd_hi[rp], p->hd_lo[rp], 256, p->cd_hi[rp], p->cd_lo[rp], 256,
            p->Wd_hi, p->Wd_lo, 512, Wdb,
            p->q, nullptr, N_HID, nullptr, 0,
            nullptr, nullptr, nullptr, nullptr, nullptr, 0, nullptr, 0, nullptr, nullptr);

        attn_dec_kernel<<<B_SZ, 256>>>(VdW, Vdb);

        // dec gates + cell (3-pass)
        mma_gemm<<<dim3(8, 8), 256, SMEM_BYTES>>>(
            2, 3, 512, 256,
            p->di_hi, p->di_lo, 256, p->hd_hi[rp], p->hd_lo[rp], 256,
            p->Gd_hi, p->Gd_lo, 512, p->bd,
            nullptr, nullptr, 0, nullptr, 0,
            p->cd_f, p->hd_hi[wp], p->hd_lo[wp],
            nullptr, nullptr, 0,
            p->hd_f, 256,
            p->cd_hi[wp], p->cd_lo[wp]);

        if (s >= DEC_STEPS - T_DEC)
            reg_kernel<<<B_SZ, 256>>>(regW, regb, out, s - (DEC_STEPS - T_DEC));
    }
}

// round 11
// speedup vs baseline: 1.3929x; 1.3342x over previous
#include <cuda_runtime.h>
#include <cuda_bf16.h>
#include <math.h>
#include <stdint.h>
#include <stddef.h>

#define B_SZ    1024
#define T_ENC   128
#define N_INP   128
#define N_HID   256
#define T_DEC   24
#define DEC_STEPS 30

typedef __nv_bfloat16 bf16;

// ===================== device buffers =====================
struct DB {
    float xi   [(size_t)B_SZ * T_ENC * N_HID];
    float mid  [(size_t)B_SZ * T_ENC * N_HID];
    bf16  mid_hi[(size_t)B_SZ * T_ENC * N_HID];
    bf16  mid_lo[(size_t)B_SZ * T_ENC * N_HID];
    bf16  uex  [(size_t)B_SZ * N_INP * N_HID];
    bf16  udmid_hi[(size_t)B_SZ * T_ENC * N_HID];
    bf16  udmid_lo[(size_t)B_SZ * T_ENC * N_HID];
    bf16  inp_hi [(size_t)B_SZ * T_ENC * N_INP];
    bf16  inp_lo [(size_t)B_SZ * T_ENC * N_INP];
    bf16  inpT_hi[(size_t)B_SZ * N_INP * T_ENC];
    bf16  inpT_lo[(size_t)B_SZ * N_INP * T_ENC];
    bf16  We_hi[256 * 512],  We_lo[256 * 512];
    bf16  Wd_hi[256 * 512],  Wd_lo[256 * 512];
    bf16  Ue2_hi[256 * 128], Ue2_lo[256 * 128];
    bf16  Ue_hi[256 * 128],  Ue_lo[256 * 128];
    bf16  Ud_hi[256 * 256],  Ud_lo[256 * 256];
    bf16  Ge_hi[1024 * 384], Ge_lo[1024 * 384];
    bf16  Gm_hi[1024 * 512], Gm_lo[1024 * 512];
    bf16  Gd_hi[1024 * 512], Gd_lo[1024 * 512];
    float be[1024], bm[1024], bd[1024];
    float ce_f[B_SZ * N_HID], cm_f[B_SZ * N_HID], cd_f[B_SZ * N_HID];
    float hd_f[B_SZ * N_HID];
    float q[B_SZ * N_HID];
    bf16 he_hi[2][B_SZ * N_HID], he_lo[2][B_SZ * N_HID];
    bf16 ce_hi[2][B_SZ * N_HID], ce_lo[2][B_SZ * N_HID];
    bf16 hm_hi[2][B_SZ * N_HID], hm_lo[2][B_SZ * N_HID];
    bf16 hd_hi[2][B_SZ * N_HID], hd_lo[2][B_SZ * N_HID];
    bf16 cd_hi[2][B_SZ * N_HID], cd_lo[2][B_SZ * N_HID];
    bf16 xa_hi[B_SZ * N_INP], xa_lo[B_SZ * N_INP];
    bf16 di_hi[B_SZ * N_HID], di_lo[B_SZ * N_HID];
};
__device__ DB db;

// ===================== helpers =====================
__device__ __forceinline__ float tanhfast(float x) {
    float y; asm("tanh.approx.f32 %0, %1;" : "=f"(y) : "f"(x)); return y;
}
__device__ __forceinline__ float sigf(float x) { return 1.0f / (1.0f + expf(-x)); }
__device__ __forceinline__ void splitf(float v, bf16& hi, bf16& lo) {
    hi = __float2bfloat16(v);
    lo = __float2bfloat16(v - __bfloat162float(hi));
}
__device__ __forceinline__ uint32_t s2u(const void* p) {
    uint32_t a;
    asm("{ .reg .u64 t; cvta.to.shared.u64 t, %1; cvt.u32.u64 %0, t; }" : "=r"(a) : "l"(p));
    return a;
}
__device__ __forceinline__ void cp16(uint32_t saddr, const void* g) {
    asm volatile("cp.async.cg.shared.global [%0], [%1], 16;" :: "r"(saddr), "l"(g));
}
__device__ __forceinline__ void mma16816(float* d, uint32_t a0, uint32_t a1,
                                         uint32_t a2, uint32_t a3,
                                         uint32_t b0, uint32_t b1) {
    asm volatile("mma.sync.aligned.m16n8k16.row.col.f32.bf16.bf16.f32 "
        "{%0,%1,%2,%3}, {%4,%5,%6,%7}, {%8,%9}, {%0,%1,%2,%3};"
        : "+f"(d[0]), "+f"(d[1]), "+f"(d[2]), "+f"(d[3])
        : "r"(a0), "r"(a1), "r"(a2), "r"(a3), "r"(b0), "r"(b1));
}

// smem: 2 stages x [A_hi(64r) | A_lo(64r) | W_hi(128r) | W_lo(128r)], 144B rows
#define STAGE_BYTES 55296
#define STAGE_WORDS 13824
#define SMEM_BYTES  110592
// word bases within stage
#define WB_AHI 0
#define WB_ALO 2304
#define WB_WHI 4608
#define WB_WLO 9216

// ===================== HMMA GEMM + fused epilogues =====================
// CTA tile 64(M) x 128(N). grid.x = N/128, grid.y = M/64.
// Y = A[M,K] * W[N,K]^T; A = concat(A1,A2) along K; bf16 hi/lo splits.
// npass: 1 = Ah*Wh;  3 = Ah*Wh + Al*Wh + Ah*Wl (~fp32)
// mode 0: outf = D+bias(+addin); mode 1: outh = bf16(D+bias);
// mode 3: split (hi->outh, lo->outl);
// mode 2: LSTM cell (N gate-interleaved n=4h+g): update cst, export h/c
__global__ void __launch_bounds__(256, 1) mma_gemm(
    int mode, int npass, int Ktot, int K1,
    const bf16* __restrict__ A1h, const bf16* __restrict__ A1l, int ld1,
    const bf16* __restrict__ A2h, const bf16* __restrict__ A2l, int ld2,
    const bf16* __restrict__ Wh,  const bf16* __restrict__ Wl,  int ldw,
    const float* __restrict__ bias,
    float* __restrict__ outf, bf16* __restrict__ outh, bf16* __restrict__ outl, int ldo,
    const float* __restrict__ addin, size_t add_ld,
    float* __restrict__ cst,
    bf16* __restrict__ h_hi, bf16* __restrict__ h_lo,
    bf16* __restrict__ h2_hi, bf16* __restrict__ h2_lo, size_t h2ld,
    float* __restrict__ hf, size_t hfld,
    bf16* __restrict__ c_hi, bf16* __restrict__ c_lo)
{
    extern __shared__ char smem[];
    const uint32_t sb = s2u(smem);
    const uint32_t* sw = (const uint32_t*)smem;

    const int tid = threadIdx.x;
    const int m0 = blockIdx.y * 64;
    const int n0 = blockIdx.x * 128;
    const int w  = tid >> 5;
    const int wm = w >> 2;            // 0..1 (32-row half)
    const int wn = w & 3;             // 0..3 (32-col quarter)
    const int lane = tid & 31;
    const int qr = lane >> 2;         // 0..7
    const int qc = lane & 3;          // 0..3
    const int NC = Ktot >> 6;

    // ---- chunk loader via cp.async (flat 16B-unit distribution) ----
    auto load_chunk = [&](int ch, int stage) {
        const int k0 = ch << 6;
        const bf16 *Ah, *Al; int ldA, kkA;
        if (k0 < K1) { Ah = A1h; Al = A1l; ldA = ld1; kkA = k0; }
        else         { Ah = A2h; Al = A2l; ldA = ld2; kkA = k0 - K1; }
        const uint32_t stg = sb + stage * STAGE_BYTES;
        const int NU = (npass == 3) ? 3072 : 1536;
        for (int u = tid; u < NU; u += 256) {
            const int un = u & 7;
            int row = u >> 3;
            const bf16* g; uint32_t so;
            if (npass == 3) {
                if (u < 512)       {             g = Ah + (size_t)(m0 + row) * ldA + kkA; so = stg + row * 144; }
                else if (u < 1024) { row -= 64;  g = Al + (size_t)(m0 + row) * ldA + kkA; so = stg + 9216 + row * 144; }
                else if (u < 2048) { row -= 128; g = Wh + (size_t)(n0 + row) * ldw + k0;  so = stg + 18432 + row * 144; }
                else               { row -= 256; g = Wl + (size_t)(n0 + row) * ldw + k0;  so = stg + 36864 + row * 144; }
            } else {
                if (u < 512)       {             g = Ah + (size_t)(m0 + row) * ldA + kkA; so = stg + row * 144; }
                else               { row -= 64;  g = Wh + (size_t)(n0 + row) * ldw + k0;  so = stg + 18432 + row * 144; }
            }
            cp16(so + un * 16, (const char*)g + un * 16);
        }
    };

    float acc[2][4][4] = {};

    load_chunk(0, 0);
    asm volatile("cp.async.commit_group;");

    for (int ch = 0; ch < NC; ch++) {
        const int stage = ch & 1;
        if (ch + 1 < NC) {
            load_chunk(ch + 1, stage ^ 1);
            asm volatile("cp.async.commit_group;");
            asm volatile("cp.async.wait_group 1;");
        } else {
            asm volatile("cp.async.wait_group 0;");
        }
        __syncthreads();

        const uint32_t* S = sw + stage * STAGE_WORDS;
        #pragma unroll
        for (int kk = 0; kk < 4; kk++) {
            const int pa = kk * 8 + qc;
            uint32_t bh[4][2], bl[4][2];
            #pragma unroll
            for (int nt = 0; nt < 4; nt++) {
                const int rB = (wn * 32 + nt * 8 + qr) * 36;
                bh[nt][0] = S[WB_WHI + rB + pa];
                bh[nt][1] = S[WB_WHI + rB + pa + 4];
                if (npass == 3) {
                    bl[nt][0] = S[WB_WLO + rB + pa];
                    bl[nt][1] = S[WB_WLO + rB + pa + 4];
                }
            }
            #pragma unroll
            for (int mt = 0; mt < 2; mt++) {
                const int rA  = (wm * 32 + mt * 16 + qr) * 36;
                const int rA8 = rA + 288;
                uint32_t ah0 = S[WB_AHI + rA + pa],     ah1 = S[WB_AHI + rA8 + pa];
                uint32_t ah2 = S[WB_AHI + rA + pa + 4], ah3 = S[WB_AHI + rA8 + pa + 4];
                #pragma unroll
                for (int nt = 0; nt < 4; nt++)
                    mma16816(acc[mt][nt], ah0, ah1, ah2, ah3, bh[nt][0], bh[nt][1]);
                if (npass == 3) {
                    uint32_t al0 = S[WB_ALO + rA + pa],     al1 = S[WB_ALO + rA8 + pa];
                    uint32_t al2 = S[WB_ALO + rA + pa + 4], al3 = S[WB_ALO + rA8 + pa + 4];
                    #pragma unroll
                    for (int nt = 0; nt < 4; nt++)
                        mma16816(acc[mt][nt], al0, al1, al2, al3, bh[nt][0], bh[nt][1]);
                    #pragma unroll
                    for (int nt = 0; nt < 4; nt++)
                        mma16816(acc[mt][nt], ah0, ah1, ah2, ah3, bl[nt][0], bl[nt][1]);
                }
            }
        }
        __syncthreads();
    }

    // ===================== epilogue =====================
    if (mode == 2) {
        #pragma unroll
        for (int mt = 0; mt < 2; mt++) {
            #pragma unroll
            for (int nt = 0; nt < 4; nt++) {
                float* d = acc[mt][nt];
                float p0 = __shfl_xor_sync(0xffffffffu, d[0], 1);
                float p1 = __shfl_xor_sync(0xffffffffu, d[1], 1);
                float p2 = __shfl_xor_sync(0xffffffffu, d[2], 1);
                float p3 = __shfl_xor_sync(0xffffffffu, d[3], 1);
                const int nbase = n0 + wn * 32 + nt * 8;
                const int hglob = (nbase >> 2) + (qc >> 1);
                const int nb4   = nbase + (qc >> 1) * 4;
                int row; float g0, g1, g2v, g3v;
                if ((qc & 1) == 0) {
                    row = m0 + wm * 32 + mt * 16 + qr;
                    g0 = d[0]; g1 = d[1]; g2v = p0; g3v = p1;
                } else {
                    row = m0 + wm * 32 + mt * 16 + qr + 8;
                    g0 = p2; g1 = p3; g2v = d[2]; g3v = d[3];
                }
                float gi = g0  + bias[nb4 + 0];
                float gf = g1  + bias[nb4 + 1];
                float gg = g2v + bias[nb4 + 2];
                float go = g3v + bias[nb4 + 3];
                const size_t off = (size_t)row * N_HID + hglob;
                float c2 = sigf(gf) * cst[off] + sigf(gi) * tanhf(gg);
                float h2 = sigf(go) * tanhf(c2);
                cst[off] = c2;
                bf16 hh, hl; splitf(h2, hh, hl);
                h_hi[off] = hh; h_lo[off] = hl;
                if (h2_hi) {
                    size_t o2 = (size_t)row * h2ld + hglob;
                    h2_hi[o2] = hh; h2_lo[o2] = hl;
                }
                if (hf) hf[(size_t)row * hfld + hglob] = h2;
                if (c_hi) {
                    bf16 ch_, cl_; splitf(c2, ch_, cl_);
                    c_hi[off] = ch_; c_lo[off] = cl_;
                }
            }
        }
    } else {
        #pragma unroll
        for (int mt = 0; mt < 2; mt++) {
            #pragma unroll
            for (int nt = 0; nt < 4; nt++) {
                float* d = acc[mt][nt];
                const size_t mr = (size_t)(m0 + wm * 32 + mt * 16 + qr);
                const int nc = n0 + wn * 32 + nt * 8 + qc * 2;
                float b0 = bias[nc], b1 = bias[nc + 1];
                float v00 = d[0] + b0, v01 = d[1] + b1;
                float v10 = d[2] + b0, v11 = d[3] + b1;
                if (addin) {
                    v00 += addin[mr * add_ld + nc];
                    v01 += addin[mr * add_ld + nc + 1];
                    v10 += addin[(mr + 8) * add_ld + nc];
                    v11 += addin[(mr + 8) * add_ld + nc + 1];
                }
                if (mode == 0) {
                    outf[mr * ldo + nc] = v00;       outf[mr * ldo + nc + 1] = v01;
                    outf[(mr + 8) * ldo + nc] = v10; outf[(mr + 8) * ldo + nc + 1] = v11;
                } else if (mode == 1) {
                    outh[mr * ldo + nc] = __float2bfloat16(v00);
                    outh[mr * ldo + nc + 1] = __float2bfloat16(v01);
                    outh[(mr + 8) * ldo + nc] = __float2bfloat16(v10);
                    outh[(mr + 8) * ldo + nc + 1] = __float2bfloat16(v11);
                } else {
                    bf16 h_, l_;
                    splitf(v00, h_, l_); outh[mr * ldo + nc] = h_;           outl[mr * ldo + nc] = l_;
                    splitf(v01, h_, l_); outh[mr * ldo + nc + 1] = h_;       outl[mr * ldo + nc + 1] = l_;
                    splitf(v10, h_, l_); outh[(mr + 8) * ldo + nc] = h_;     outl[(mr + 8) * ldo + nc] = l_;
                    splitf(v11, h_, l_); outh[(mr + 8) * ldo + nc + 1] = h_; outl[(mr + 8) * ldo + nc + 1] = l_;
                }
            }
        }
    }
}

// ===================== prep kernels =====================
__global__ void init_state_kernel() {
    int i = blockIdx.x * 256 + threadIdx.x;
    bf16 z = __float2bfloat16(0.f);
    db.ce_f[i] = 0.f; db.cm_f[i] = 0.f; db.cd_f[i] = 0.f;
    db.he_hi[0][i] = z; db.he_lo[0][i] = z;
    db.ce_hi[0][i] = z; db.ce_lo[0][i] = z;
    db.hm_hi[0][i] = z; db.hm_lo[0][i] = z;
    db.hd_hi[0][i] = z; db.hd_lo[0][i] = z;
    db.cd_hi[0][i] = z; db.cd_lo[0][i] = z;
}

__global__ void split_arr(const float* __restrict__ src, bf16* __restrict__ hi,
                          bf16* __restrict__ lo, int n) {
    int i = blockIdx.x * 256 + threadIdx.x;
    if (i >= n) return;
    splitf(src[i], hi[i], lo[i]);
}

__global__ void gates_prep(const float* __restrict__ Wih, int Ki,
                           const float* __restrict__ Whh,
                           const float* __restrict__ bih, const float* __restrict__ bhh,
                           bf16* __restrict__ Whi, bf16* __restrict__ Wlo,
                           float* __restrict__ br, int Kt)
{
    int idx = blockIdx.x * 256 + threadIdx.x;
    if (idx >= 1024 * Kt) return;
    int nrow = idx / Kt, k = idx - nrow * Kt;
    int h = nrow >> 2, g = nrow & 3;
    float v = (k < Ki) ? Wih[(size_t)(g * 256 + h) * Ki + k]
                       : Whh[(size_t)(g * 256 + h) * 256 + (k - Ki)];
    splitf(v, Whi[idx], Wlo[idx]);
    if (k == 0) br[nrow] = bih[g * 256 + h] + bhh[g * 256 + h];
}

// transpose inp[b][t][j] -> inpT[b][j][t] (split bf16)
__global__ void __launch_bounds__(256) transpose_split_kernel(const float* __restrict__ inp) {
    __shared__ float tile[32][33];
    const int b  = blockIdx.x;
    const int tx = threadIdx.x & 31, ty = threadIdx.x >> 5;   // 32 x 8
    const float* ib = inp + (size_t)b * (T_ENC * N_INP);
    for (int tt = 0; tt < 4; tt++)
        for (int jj = 0; jj < 4; jj++) {
            #pragma unroll
            for (int r = 0; r < 4; r++) {
                int t = tt * 32 + ty + r * 8, j = jj * 32 + tx;
                tile[ty + r * 8][tx] = ib[t * N_INP + j];
            }
            __syncthreads();
            #pragma unroll
            for (int r = 0; r < 4; r++) {
                int j = jj * 32 + ty + r * 8, t = tt * 32 + tx;
                bf16 hi, lo; splitf(tile[tx][ty + r * 8], hi, lo);
                size_t o = (size_t)b * (N_INP * T_ENC) + (size_t)j * T_ENC + t;
                db.inpT_hi[o] = hi; db.inpT_lo[o] = lo;
            }
            __syncthreads();
        }
}

// ===================== attention kernels =====================
__global__ void __launch_bounds__(256) attn_enc_kernel(
    const float* __restrict__ inp, const float* __restrict__ VeW,
    const float* __restrict__ VeB, int t)
{
    const int b = blockIdx.x;
    const int tid = threadIdx.x;
    const int lane = tid & 31;
    const int w = tid >> 5;

    __shared__ float sq[256], sv[256], ssc[128], sred[256];
    sq[tid] = db.q[(size_t)b * N_HID + tid];
    sv[tid] = VeW[tid];
    __syncthreads();

    const bf16* ub = db.uex + (size_t)b * (N_INP * N_HID);
    const float veb = VeB[0];

    for (int j = w; j < N_INP; j += 8) {
        const __nv_bfloat162* up = (const __nv_bfloat162*)(ub + (size_t)j * N_HID);
        float s = 0.f;
        #pragma unroll
        for (int i = 0; i < 4; i++) {
            __nv_bfloat162 u2 = up[lane + 32 * i];
            int k = 64 * i + 2 * lane;
            s += sv[k]     * tanhfast(sq[k]     + __low2float(u2));
            s += sv[k + 1] * tanhfast(sq[k + 1] + __high2float(u2));
        }
        #pragma unroll
        for (int o = 16; o > 0; o >>= 1) s += __shfl_xor_sync(0xffffffffu, s, o);
        if (lane == 0) ssc[j] = s + veb;
    }
    __syncthreads();

    float x = (tid < 128) ? ssc[tid] : -1e30f;
    sred[tid] = x; __syncthreads();
    #pragma unroll
    for (int o = 128; o > 0; o >>= 1) {
        if (tid < o) sred[tid] = fmaxf(sred[tid], sred[tid + o]);
        __syncthreads();
    }
    float mx = sred[0];
    __syncthreads();
    float e = (tid < 128) ? expf(x - mx) : 0.f;
    sred[tid] = e; __syncthreads();
    #pragma unroll
    for (int o = 128; o > 0; o >>= 1) {
        if (tid < o) sred[tid] += sred[tid + o];
        __syncthreads();
    }
    float inv = 1.0f / sred[0];
    if (tid < 128) {
        float xv = inp[((size_t)b * T_ENC + t) * N_INP + tid];
        bf16 hh, hl; splitf(xv * e * inv, hh, hl);
        db.xa_hi[(size_t)b * N_INP + tid] = hh;
        db.xa_lo[(size_t)b * N_INP + tid] = hl;
    }
}

__global__ void __launch_bounds__(256) attn_dec_kernel(
    const float* __restrict__ VdW, const float* __restrict__ VdB)
{
    const int b = blockIdx.x;
    const int tid = threadIdx.x;
    const int lane = tid & 31;
    const int w = tid >> 5;

    __shared__ float sq[256], sv[256], st[128];
    sq[tid] = db.q[(size_t)b * N_HID + tid];
    sv[tid] = VdW[tid];
    __syncthreads();

    const bf16* ubh = db.udmid_hi + (size_t)b * (T_ENC * N_HID);
    const bf16* ubl = db.udmid_lo + (size_t)b * (T_ENC * N_HID);
    const float vdb = VdB[0];

    for (int j = w; j < T_ENC; j += 8) {
        const __nv_bfloat162* uph = (const __nv_bfloat162*)(ubh + (size_t)j * N_HID);
        const __nv_bfloat162* upl = (const __nv_bfloat162*)(ubl + (size_t)j * N_HID);
        float s = 0.f;
        #pragma unroll
        for (int i = 0; i < 4; i++) {
            __nv_bfloat162 u2 = uph[lane + 32 * i];
            __nv_bfloat162 l2 = upl[lane + 32 * i];
            int k = 64 * i + 2 * lane;
            s += sv[k]     * tanhfast(sq[k]     + __low2float(u2)  + __low2float(l2));
            s += sv[k + 1] * tanhfast(sq[k + 1] + __high2float(u2) + __high2float(l2));
        }
        #pragma unroll
        for (int o = 16; o > 0; o >>= 1) s += __shfl_xor_sync(0xffffffffu, s, o);
        if (lane == 0) st[j] = s + vdb;
    }
    __syncthreads();

    const float* mb = db.mid + (size_t)b * (T_ENC * N_HID) + tid;
    float acc = 0.f;
    #pragma unroll 8
    for (int j = 0; j < T_ENC; j++)
        acc += st[j] * mb[(size_t)j * N_HID];
    bf16 hh, hl; splitf(acc, hh, hl);
    db.di_hi[(size_t)b * N_HID + tid] = hh;
    db.di_lo[(size_t)b * N_HID + tid] = hl;
}

// ===================== regression output =====================
__global__ void __launch_bounds__(256) reg_kernel(
    const float* __restrict__ regW, const float* __restrict__ regB,
    float* __restrict__ out, int col)
{
    const int b = blockIdx.x;
    const int n = threadIdx.x;
    __shared__ float sr[256];
    sr[n] = regW[n] * db.hd_f[(size_t)b * N_HID + n];
    __syncthreads();
    #pragma unroll
    for (int o = 128; o > 0; o >>= 1) {
        if (n < o) sr[n] += sr[n + o];
        __syncthreads();
    }
    if (n == 0) out[(size_t)b * T_DEC + col] = sr[0] + regB[0];
}

// ===================== host launcher =====================
extern "C" void kernel_launch(void* const* d_in, const int* in_sizes, int n_in,
                              void* d_out, int out_size)
{
    (void)in_sizes; (void)n_in; (void)out_size;
    const float* inp  = (const float*)d_in[0];
    const float* UeW  = (const float*)d_in[2];
    const float* Ueb  = (const float*)d_in[3];
    const float* Ue2W = (const float*)d_in[4];
    const float* Ue2b = (const float*)d_in[5];
    const float* WeW  = (const float*)d_in[6];
    const float* Web  = (const float*)d_in[7];
    const float* VeW  = (const float*)d_in[8];
    const float* Veb  = (const float*)d_in[9];
    const float* UdW  = (const float*)d_in[10];
    const float* Udb  = (const float*)d_in[11];
    const float* WdW  = (const float*)d_in[12];
    const float* Wdb  = (const float*)d_in[13];
    const float* VdW  = (const float*)d_in[14];
    const float* Vdb  = (const float*)d_in[15];
    const float* eWih = (const float*)d_in[16];
    const float* eWhh = (const float*)d_in[17];
    const float* ebih = (const float*)d_in[18];
    const float* ebhh = (const float*)d_in[19];
    const float* mWih = (const float*)d_in[20];
    const float* mWhh = (const float*)d_in[21];
    const float* mbih = (const float*)d_in[22];
    const float* mbhh = (const float*)d_in[23];
    const float* dWih = (const float*)d_in[24];
    const float* dWhh = (const float*)d_in[25];
    const float* dbih = (const float*)d_in[26];
    const float* dbhh = (const float*)d_in[27];
    const float* regW = (const float*)d_in[28];
    const float* regb = (const float*)d_in[29];
    float* out = (float*)d_out;

    cudaFuncSetAttribute(mma_gemm, cudaFuncAttributeMaxDynamicSharedMemorySize, SMEM_BYTES);

    DB* p;
    cudaGetSymbolAddress((void**)&p, db);

    init_state_kernel<<<1024, 256>>>();

    split_arr<<<(B_SZ * T_ENC * N_INP + 255) / 256, 256>>>(inp, p->inp_hi, p->inp_lo, B_SZ * T_ENC * N_INP);
    split_arr<<<(256 * 512 + 255) / 256, 256>>>(WeW,  p->We_hi,  p->We_lo,  256 * 512);
    split_arr<<<(256 * 512 + 255) / 256, 256>>>(WdW,  p->Wd_hi,  p->Wd_lo,  256 * 512);
    split_arr<<<(256 * 128 + 255) / 256, 256>>>(Ue2W, p->Ue2_hi, p->Ue2_lo, 256 * 128);
    split_arr<<<(256 * 128 + 255) / 256, 256>>>(UeW,  p->Ue_hi,  p->Ue_lo,  256 * 128);
    split_arr<<<(256 * 256 + 255) / 256, 256>>>(UdW,  p->Ud_hi,  p->Ud_lo,  256 * 256);
    gates_prep<<<(1024 * 384 + 255) / 256, 256>>>(eWih, 128, eWhh, ebih, ebhh, p->Ge_hi, p->Ge_lo, p->be, 384);
    gates_prep<<<(1024 * 512 + 255) / 256, 256>>>(mWih, 256, mWhh, mbih, mbhh, p->Gm_hi, p->Gm_lo, p->bm, 512);
    gates_prep<<<(1024 * 512 + 255) / 256, 256>>>(dWih, 256, dWhh, dbih, dbhh, p->Gd_hi, p->Gd_lo, p->bd, 512);

    transpose_split_kernel<<<B_SZ, 256>>>(inp);

    // xi = inp @ Ue2^T + b   (3-pass, fp32 out)  M = B*T
    mma_gemm<<<dim3(2, 2048), 256, SMEM_BYTES>>>(
        0, 3, 128, 128,
        p->inp_hi, p->inp_lo, 128, nullptr, nullptr, 0,
        p->Ue2_hi, p->Ue2_lo, 128, Ue2b,
        p->xi, nullptr, nullptr, N_HID, nullptr, 0,
        nullptr, nullptr, nullptr, nullptr, nullptr, 0, nullptr, 0, nullptr, nullptr);

    // uex = inpT @ Ue^T + b  (3-pass, bf16 out)  M = B*128 rows (b,j)
    mma_gemm<<<dim3(2, 2048), 256, SMEM_BYTES>>>(
        1, 3, 128, 128,
        p->inpT_hi, p->inpT_lo, 128, nullptr, nullptr, 0,
        p->Ue_hi, p->Ue_lo, 128, Ueb,
        nullptr, p->uex, nullptr, N_HID, nullptr, 0,
        nullptr, nullptr, nullptr, nullptr, nullptr, 0, nullptr, 0, nullptr, nullptr);

    // -------- encoder + mid recurrence --------
    for (int t = 0; t < T_ENC; t++) {
        int rp = t & 1, wp = rp ^ 1;
        // q = Web + [h|c] @ We^T + xi[:,t,:]   (3-pass)
        mma_gemm<<<dim3(2, 16), 256, SMEM_BYTES>>>(
            0, 3, 512, 256,
            p->he_hi[rp], p->he_lo[rp], 256, p->ce_hi[rp], p->ce_lo[rp], 256,
            p->We_hi, p->We_lo, 512, Web,
            p->q, nullptr, nullptr, N_HID, p->xi + (size_t)t * N_HID, (size_t)T_ENC * N_HID,
            nullptr, nullptr, nullptr, nullptr, nullptr, 0, nullptr, 0, nullptr, nullptr);

        attn_enc_kernel<<<B_SZ, 256>>>(inp, VeW, Veb, t);

        // enc gates + cell (3-pass)
        mma_gemm<<<dim3(8, 16), 256, SMEM_BYTES>>>(
            2, 3, 384, 128,
            p->xa_hi, p->xa_lo, 128, p->he_hi[rp], p->he_lo[rp], 256,
            p->Ge_hi, p->Ge_lo, 384, p->be,
            nullptr, nullptr, nullptr, 0, nullptr, 0,
            p->ce_f, p->he_hi[wp], p->he_lo[wp],
            nullptr, nullptr, 0, nullptr, 0,
            p->ce_hi[wp], p->ce_lo[wp]);

        // mid gates + cell (3-pass), exports mid[t] fp32 + hi/lo
        mma_gemm<<<dim3(8, 16), 256, SMEM_BYTES>>>(
            2, 3, 512, 256,
            p->he_hi[wp], p->he_lo[wp], 256, p->hm_hi[rp], p->hm_lo[rp], 256,
            p->Gm_hi, p->Gm_lo, 512, p->bm,
            nullptr, nullptr, nullptr, 0, nullptr, 0,
            p->cm_f, p->hm_hi[wp], p->hm_lo[wp],
            p->mid_hi + (size_t)t * N_HID, p->mid_lo + (size_t)t * N_HID, (size_t)T_ENC * N_HID,
            p->mid + (size_t)t * N_HID, (size_t)T_ENC * N_HID,
            nullptr, nullptr);
    }

    // ud_mid = mid @ Ud^T + b  (3-pass, split hi/lo out)
    mma_gemm<<<dim3(2, 2048), 256, SMEM_BYTES>>>(
        3, 3, 256, 256,
        p->mid_hi, p->mid_lo, 256, nullptr, nullptr, 0,
        p->Ud_hi, p->Ud_lo, 256, Udb,
        nullptr, p->udmid_hi, p->udmid_lo, N_HID, nullptr, 0,
        nullptr, nullptr, nullptr, nullptr, nullptr, 0, nullptr, 0, nullptr, nullptr);

    // -------- decoder --------
    for (int s = 0; s < DEC_STEPS; s++) {
        int rp = s & 1, wp = rp ^ 1;
        // wd = Wdb + [hd|cd] @ Wd^T  (3-pass)
        mma_gemm<<<dim3(2, 16), 256, SMEM_BYTES>>>(
            0, 3, 512, 256,
            p->hd_hi[rp], p->hd_lo[rp], 256, p->cd_hi[rp], p->cd_lo[rp], 256,
            p->Wd_hi, p->Wd_lo, 512, Wdb,
            p->q, nullptr, nullptr, N_HID, nullptr, 0,
            nullptr, nullptr, nullptr, nullptr, nullptr, 0, nullptr, 0, nullptr, nullptr);

        attn_dec_kernel<<<B_SZ, 256>>>(VdW, Vdb);

        // dec gates + cell (3-pass)
        mma_gemm<<<dim3(8, 16), 256, SMEM_BYTES>>>(
            2, 3, 512, 256,
            p->di_hi, p->di_lo, 256, p->hd_hi[rp], p->hd_lo[rp], 256,
            p->Gd_hi, p->Gd_lo, 512, p->bd,
            nullptr, nullptr, nullptr, 0, nullptr, 0,
            p->cd_f, p->hd_hi[wp], p->hd_lo[wp],
            nullptr, nullptr, 0,
            p->hd_f, 256,
            p->cd_hi[wp], p->cd_lo[wp]);

        if (s >= DEC_STEPS - T_DEC)
            reg_kernel<<<B_SZ, 256>>>(regW, regb, out, s - (DEC_STEPS - T_DEC));
    }
}

// round 12
// speedup vs baseline: 1.6251x; 1.1667x over previous
#include <cuda_runtime.h>
#include <cuda_bf16.h>
#include <math.h>
#include <stdint.h>
#include <stddef.h>

#define B_SZ    1024
#define T_ENC   128
#define N_INP   128
#define N_HID   256
#define T_DEC   24
#define DEC_STEPS 30

typedef __nv_bfloat16 bf16;

// ===================== device buffers =====================
struct DB {
    float xi   [(size_t)B_SZ * T_ENC * N_HID];
    float mid  [(size_t)B_SZ * T_ENC * N_HID];
    bf16  mid_hi[(size_t)B_SZ * T_ENC * N_HID];
    bf16  mid_lo[(size_t)B_SZ * T_ENC * N_HID];
    bf16  uex  [(size_t)B_SZ * N_INP * N_HID];
    bf16  udmid_hi[(size_t)B_SZ * T_ENC * N_HID];
    bf16  udmid_lo[(size_t)B_SZ * T_ENC * N_HID];
    bf16  inp_hi [(size_t)B_SZ * T_ENC * N_INP];
    bf16  inp_lo [(size_t)B_SZ * T_ENC * N_INP];
    bf16  inpT_hi[(size_t)B_SZ * N_INP * T_ENC];
    bf16  inpT_lo[(size_t)B_SZ * N_INP * T_ENC];
    bf16  We_hi[256 * 512],  We_lo[256 * 512];
    bf16  Wd_hi[256 * 512],  Wd_lo[256 * 512];
    bf16  Ue2_hi[256 * 128], Ue2_lo[256 * 128];
    bf16  Ue_hi[256 * 128],  Ue_lo[256 * 128];
    bf16  Ud_hi[256 * 256],  Ud_lo[256 * 256];
    bf16  Ge_hi[1024 * 384], Ge_lo[1024 * 384];
    bf16  Gm_hi[1024 * 512], Gm_lo[1024 * 512];
    bf16  Gd_hi[1024 * 512], Gd_lo[1024 * 512];
    float be[1024], bm[1024], bd[1024];
    float ce_f[B_SZ * N_HID], cm_f[B_SZ * N_HID], cd_f[B_SZ * N_HID];
    float hd_f[B_SZ * N_HID];
    float q[B_SZ * N_HID];
    bf16 he_hi[2][B_SZ * N_HID], he_lo[2][B_SZ * N_HID];
    bf16 ce_hi[2][B_SZ * N_HID], ce_lo[2][B_SZ * N_HID];
    bf16 hm_hi[2][B_SZ * N_HID], hm_lo[2][B_SZ * N_HID];
    bf16 hd_hi[2][B_SZ * N_HID], hd_lo[2][B_SZ * N_HID];
    bf16 cd_hi[2][B_SZ * N_HID], cd_lo[2][B_SZ * N_HID];
    bf16 xa_hi[B_SZ * N_INP], xa_lo[B_SZ * N_INP];
    bf16 di_hi[B_SZ * N_HID], di_lo[B_SZ * N_HID];
};
__device__ DB db;

// ===================== helpers =====================
__device__ __forceinline__ float tanhfast(float x) {
    float y; asm("tanh.approx.f32 %0, %1;" : "=f"(y) : "f"(x)); return y;
}
__device__ __forceinline__ float sigf(float x) { return 1.0f / (1.0f + expf(-x)); }
__device__ __forceinline__ void splitf(float v, bf16& hi, bf16& lo) {
    hi = __float2bfloat16(v);
    lo = __float2bfloat16(v - __bfloat162float(hi));
}
__device__ __forceinline__ uint32_t s2u(const void* p) {
    uint32_t a;
    asm("{ .reg .u64 t; cvta.to.shared.u64 t, %1; cvt.u32.u64 %0, t; }" : "=r"(a) : "l"(p));
    return a;
}
__device__ __forceinline__ void cp16(uint32_t saddr, const void* g) {
    asm volatile("cp.async.cg.shared.global [%0], [%1], 16;" :: "r"(saddr), "l"(g));
}
__device__ __forceinline__ void mma16816(float* d, uint32_t a0, uint32_t a1,
                                         uint32_t a2, uint32_t a3,
                                         uint32_t b0, uint32_t b1) {
    asm volatile("mma.sync.aligned.m16n8k16.row.col.f32.bf16.bf16.f32 "
        "{%0,%1,%2,%3}, {%4,%5,%6,%7}, {%8,%9}, {%0,%1,%2,%3};"
        : "+f"(d[0]), "+f"(d[1]), "+f"(d[2]), "+f"(d[3])
        : "r"(a0), "r"(a1), "r"(a2), "r"(a3), "r"(b0), "r"(b1));
}

// smem: 2 stages x [A_hi(64r) | A_lo(64r) | W_hi(128r) | W_lo(128r)], 144B rows
#define STAGE_BYTES 55296
#define STAGE_WORDS 13824
#define SMEM_BYTES  110592
#define WB_AHI 0
#define WB_ALO 2304
#define WB_WHI 4608
#define WB_WLO 9216

// ===================== GEMM body (device fn; m0/n0 passed in) ================
__device__ void gemm_body(
    char* smem, int m0, int n0,
    int mode, int npass, int Ktot, int K1,
    const bf16* __restrict__ A1h, const bf16* __restrict__ A1l, int ld1,
    const bf16* __restrict__ A2h, const bf16* __restrict__ A2l, int ld2,
    const bf16* __restrict__ Wh,  const bf16* __restrict__ Wl,  int ldw,
    const float* __restrict__ bias,
    float* __restrict__ outf, bf16* __restrict__ outh, bf16* __restrict__ outl, int ldo,
    const float* __restrict__ addin, size_t add_ld,
    float* __restrict__ cst,
    bf16* __restrict__ h_hi, bf16* __restrict__ h_lo,
    bf16* __restrict__ h2_hi, bf16* __restrict__ h2_lo, size_t h2ld,
    float* __restrict__ hf, size_t hfld,
    bf16* __restrict__ c_hi, bf16* __restrict__ c_lo)
{
    const uint32_t sb = s2u(smem);
    const uint32_t* sw = (const uint32_t*)smem;

    const int tid = threadIdx.x;
    const int w  = tid >> 5;
    const int wm = w >> 2;
    const int wn = w & 3;
    const int lane = tid & 31;
    const int qr = lane >> 2;
    const int qc = lane & 3;
    const int NC = Ktot >> 6;

    auto load_chunk = [&](int ch, int stage) {
        const int k0 = ch << 6;
        const bf16 *Ah, *Al; int ldA, kkA;
        if (k0 < K1) { Ah = A1h; Al = A1l; ldA = ld1; kkA = k0; }
        else         { Ah = A2h; Al = A2l; ldA = ld2; kkA = k0 - K1; }
        const uint32_t stg = sb + stage * STAGE_BYTES;
        const int NU = (npass == 3) ? 3072 : 1536;
        for (int u = tid; u < NU; u += 256) {
            const int un = u & 7;
            int row = u >> 3;
            const bf16* g; uint32_t so;
            if (npass == 3) {
                if (u < 512)       {             g = Ah + (size_t)(m0 + row) * ldA + kkA; so = stg + row * 144; }
                else if (u < 1024) { row -= 64;  g = Al + (size_t)(m0 + row) * ldA + kkA; so = stg + 9216 + row * 144; }
                else if (u < 2048) { row -= 128; g = Wh + (size_t)(n0 + row) * ldw + k0;  so = stg + 18432 + row * 144; }
                else               { row -= 256; g = Wl + (size_t)(n0 + row) * ldw + k0;  so = stg + 36864 + row * 144; }
            } else {
                if (u < 512)       {             g = Ah + (size_t)(m0 + row) * ldA + kkA; so = stg + row * 144; }
                else               { row -= 64;  g = Wh + (size_t)(n0 + row) * ldw + k0;  so = stg + 18432 + row * 144; }
            }
            cp16(so + un * 16, (const char*)g + un * 16);
        }
    };

    float acc[2][4][4] = {};

    load_chunk(0, 0);
    asm volatile("cp.async.commit_group;");

    for (int ch = 0; ch < NC; ch++) {
        const int stage = ch & 1;
        if (ch + 1 < NC) {
            load_chunk(ch + 1, stage ^ 1);
            asm volatile("cp.async.commit_group;");
            asm volatile("cp.async.wait_group 1;");
        } else {
            asm volatile("cp.async.wait_group 0;");
        }
        __syncthreads();

        const uint32_t* S = sw + stage * STAGE_WORDS;
        #pragma unroll
        for (int kk = 0; kk < 4; kk++) {
            const int pa = kk * 8 + qc;
            uint32_t bh[4][2], bl[4][2];
            #pragma unroll
            for (int nt = 0; nt < 4; nt++) {
                const int rB = (wn * 32 + nt * 8 + qr) * 36;
                bh[nt][0] = S[WB_WHI + rB + pa];
                bh[nt][1] = S[WB_WHI + rB + pa + 4];
                if (npass == 3) {
                    bl[nt][0] = S[WB_WLO + rB + pa];
                    bl[nt][1] = S[WB_WLO + rB + pa + 4];
                }
            }
            #pragma unroll
            for (int mt = 0; mt < 2; mt++) {
                const int rA  = (wm * 32 + mt * 16 + qr) * 36;
                const int rA8 = rA + 288;
                uint32_t ah0 = S[WB_AHI + rA + pa],     ah1 = S[WB_AHI + rA8 + pa];
                uint32_t ah2 = S[WB_AHI + rA + pa + 4], ah3 = S[WB_AHI + rA8 + pa + 4];
                #pragma unroll
                for (int nt = 0; nt < 4; nt++)
                    mma16816(acc[mt][nt], ah0, ah1, ah2, ah3, bh[nt][0], bh[nt][1]);
                if (npass == 3) {
                    uint32_t al0 = S[WB_ALO + rA + pa],     al1 = S[WB_ALO + rA8 + pa];
                    uint32_t al2 = S[WB_ALO + rA + pa + 4], al3 = S[WB_ALO + rA8 + pa + 4];
                    #pragma unroll
                    for (int nt = 0; nt < 4; nt++)
                        mma16816(acc[mt][nt], al0, al1, al2, al3, bh[nt][0], bh[nt][1]);
                    #pragma unroll
                    for (int nt = 0; nt < 4; nt++)
                        mma16816(acc[mt][nt], ah0, ah1, ah2, ah3, bl[nt][0], bl[nt][1]);
                }
            }
        }
        __syncthreads();
    }

    if (mode == 2) {
        #pragma unroll
        for (int mt = 0; mt < 2; mt++) {
            #pragma unroll
            for (int nt = 0; nt < 4; nt++) {
                float* d = acc[mt][nt];
                float p0 = __shfl_xor_sync(0xffffffffu, d[0], 1);
                float p1 = __shfl_xor_sync(0xffffffffu, d[1], 1);
                float p2 = __shfl_xor_sync(0xffffffffu, d[2], 1);
                float p3 = __shfl_xor_sync(0xffffffffu, d[3], 1);
                const int nbase = n0 + wn * 32 + nt * 8;
                const int hglob = (nbase >> 2) + (qc >> 1);
                const int nb4   = nbase + (qc >> 1) * 4;
                int row; float g0, g1, g2v, g3v;
                if ((qc & 1) == 0) {
                    row = m0 + wm * 32 + mt * 16 + qr;
                    g0 = d[0]; g1 = d[1]; g2v = p0; g3v = p1;
                } else {
                    row = m0 + wm * 32 + mt * 16 + qr + 8;
                    g0 = p2; g1 = p3; g2v = d[2]; g3v = d[3];
                }
                float gi = g0  + bias[nb4 + 0];
                float gf = g1  + bias[nb4 + 1];
                float gg = g2v + bias[nb4 + 2];
                float go = g3v + bias[nb4 + 3];
                const size_t off = (size_t)row * N_HID + hglob;
                float c2 = sigf(gf) * cst[off] + sigf(gi) * tanhf(gg);
                float h2 = sigf(go) * tanhf(c2);
                cst[off] = c2;
                bf16 hh, hl; splitf(h2, hh, hl);
                h_hi[off] = hh; h_lo[off] = hl;
                if (h2_hi) {
                    size_t o2 = (size_t)row * h2ld + hglob;
                    h2_hi[o2] = hh; h2_lo[o2] = hl;
                }
                if (hf) hf[(size_t)row * hfld + hglob] = h2;
                if (c_hi) {
                    bf16 ch_, cl_; splitf(c2, ch_, cl_);
                    c_hi[off] = ch_; c_lo[off] = cl_;
                }
            }
        }
    } else {
        #pragma unroll
        for (int mt = 0; mt < 2; mt++) {
            #pragma unroll
            for (int nt = 0; nt < 4; nt++) {
                float* d = acc[mt][nt];
                const size_t mr = (size_t)(m0 + wm * 32 + mt * 16 + qr);
                const int nc = n0 + wn * 32 + nt * 8 + qc * 2;
                float b0 = bias[nc], b1 = bias[nc + 1];
                float v00 = d[0] + b0, v01 = d[1] + b1;
                float v10 = d[2] + b0, v11 = d[3] + b1;
                if (addin) {
                    v00 += addin[mr * add_ld + nc];
                    v01 += addin[mr * add_ld + nc + 1];
                    v10 += addin[(mr + 8) * add_ld + nc];
                    v11 += addin[(mr + 8) * add_ld + nc + 1];
                }
                if (mode == 0) {
                    outf[mr * ldo + nc] = v00;       outf[mr * ldo + nc + 1] = v01;
                    outf[(mr + 8) * ldo + nc] = v10; outf[(mr + 8) * ldo + nc + 1] = v11;
                } else if (mode == 1) {
                    outh[mr * ldo + nc] = __float2bfloat16(v00);
                    outh[mr * ldo + nc + 1] = __float2bfloat16(v01);
                    outh[(mr + 8) * ldo + nc] = __float2bfloat16(v10);
                    outh[(mr + 8) * ldo + nc + 1] = __float2bfloat16(v11);
                } else {
                    bf16 h_, l_;
                    splitf(v00, h_, l_); outh[mr * ldo + nc] = h_;           outl[mr * ldo + nc] = l_;
                    splitf(v01, h_, l_); outh[mr * ldo + nc + 1] = h_;       outl[mr * ldo + nc + 1] = l_;
                    splitf(v10, h_, l_); outh[(mr + 8) * ldo + nc] = h_;     outl[(mr + 8) * ldo + nc] = l_;
                    splitf(v11, h_, l_); outh[(mr + 8) * ldo + nc + 1] = h_; outl[(mr + 8) * ldo + nc + 1] = l_;
                }
            }
        }
    }
}

// ===================== generic GEMM kernel =====================
__global__ void __launch_bounds__(256, 1) mma_gemm(
    int mode, int npass, int Ktot, int K1,
    const bf16* A1h, const bf16* A1l, int ld1,
    const bf16* A2h, const bf16* A2l, int ld2,
    const bf16* Wh,  const bf16* Wl,  int ldw,
    const float* bias,
    float* outf, bf16* outh, bf16* outl, int ldo,
    const float* addin, size_t add_ld,
    float* cst,
    bf16* h_hi, bf16* h_lo,
    bf16* h2_hi, bf16* h2_lo, size_t h2ld,
    float* hf, size_t hfld,
    bf16* c_hi, bf16* c_lo)
{
    extern __shared__ char smem[];
    gemm_body(smem, blockIdx.y * 64, blockIdx.x * 128,
              mode, npass, Ktot, K1, A1h, A1l, ld1, A2h, A2l, ld2,
              Wh, Wl, ldw, bias, outf, outh, outl, ldo, addin, add_ld,
              cst, h_hi, h_lo, h2_hi, h2_lo, h2ld, hf, hfld, c_hi, c_lo);
}

// ===================== encoder combo: q(t) + mid(t-1) =====================
// grid = 160 (flat). blocks 0..31: q GEMM. blocks 32..159: mid gates+cell.
__global__ void __launch_bounds__(256, 1) enc_combo(int t, const float* __restrict__ Web)
{
    extern __shared__ char smem[];
    DB* p = &db;
    const int rp = t & 1, wp = rp ^ 1;
    const int f = blockIdx.x;
    if (f < 32) {
        // q = Web + [he|ce](t-1) @ We^T + xi[:,t,:]
        gemm_body(smem, (f >> 1) * 64, (f & 1) * 128,
            0, 3, 512, 256,
            p->he_hi[rp], p->he_lo[rp], 256, p->ce_hi[rp], p->ce_lo[rp], 256,
            p->We_hi, p->We_lo, 512, Web,
            p->q, nullptr, nullptr, N_HID, p->xi + (size_t)t * N_HID, (size_t)T_ENC * N_HID,
            nullptr, nullptr, nullptr, nullptr, nullptr, 0, nullptr, 0, nullptr, nullptr);
    } else if (t > 0) {
        // mid gates + cell for step t-1: A = [he(t-1) | hm(t-2)]
        const int f2 = f - 32;
        gemm_body(smem, (f2 >> 3) * 64, (f2 & 7) * 128,
            2, 3, 512, 256,
            p->he_hi[rp], p->he_lo[rp], 256, p->hm_hi[wp], p->hm_lo[wp], 256,
            p->Gm_hi, p->Gm_lo, 512, p->bm,
            nullptr, nullptr, nullptr, 0, nullptr, 0,
            p->cm_f, p->hm_hi[rp], p->hm_lo[rp],
            p->mid_hi + (size_t)(t - 1) * N_HID, p->mid_lo + (size_t)(t - 1) * N_HID,
            (size_t)T_ENC * N_HID,
            p->mid + (size_t)(t - 1) * N_HID, (size_t)T_ENC * N_HID,
            nullptr, nullptr);
    }
}

// ===================== decoder combo: wd(s) + reg(s-1) =====================
__global__ void __launch_bounds__(256, 1) dec_combo(
    int s, const float* __restrict__ Wdb,
    const float* __restrict__ regW, const float* __restrict__ regB,
    float* __restrict__ out)
{
    extern __shared__ char smem[];
    DB* p = &db;
    const int rp = s & 1;
    const int f = blockIdx.x;
    if (f < 32) {
        gemm_body(smem, (f >> 1) * 64, (f & 1) * 128,
            0, 3, 512, 256,
            p->hd_hi[rp], p->hd_lo[rp], 256, p->cd_hi[rp], p->cd_lo[rp], 256,
            p->Wd_hi, p->Wd_lo, 512, Wdb,
            p->q, nullptr, nullptr, N_HID, nullptr, 0,
            nullptr, nullptr, nullptr, nullptr, nullptr, 0, nullptr, 0, nullptr, nullptr);
    } else {
        const int col = (s - 1) - (DEC_STEPS - T_DEC);
        if (s < 1 || col < 0) return;
        const int b = f - 32;
        const int n = threadIdx.x;
        float* sr = (float*)smem;
        sr[n] = regW[n] * p->hd_f[(size_t)b * N_HID + n];
        __syncthreads();
        #pragma unroll
        for (int o = 128; o > 0; o >>= 1) {
            if (n < o) sr[n] += sr[n + o];
            __syncthreads();
        }
        if (n == 0) out[(size_t)b * T_DEC + col] = sr[0] + regB[0];
    }
}

// ===================== prologue combo: xi + uex =====================
__global__ void __launch_bounds__(256, 1) prol_combo(
    const float* __restrict__ Ue2b, const float* __restrict__ Ueb)
{
    extern __shared__ char smem[];
    DB* p = &db;
    const int f = blockIdx.x;
    if (f < 4096) {
        gemm_body(smem, (f >> 1) * 64, (f & 1) * 128,
            0, 3, 128, 128,
            p->inp_hi, p->inp_lo, 128, nullptr, nullptr, 0,
            p->Ue2_hi, p->Ue2_lo, 128, Ue2b,
            p->xi, nullptr, nullptr, N_HID, nullptr, 0,
            nullptr, nullptr, nullptr, nullptr, nullptr, 0, nullptr, 0, nullptr, nullptr);
    } else {
        const int f2 = f - 4096;
        gemm_body(smem, (f2 >> 1) * 64, (f2 & 1) * 128,
            1, 3, 128, 128,
            p->inpT_hi, p->inpT_lo, 128, nullptr, nullptr, 0,
            p->Ue_hi, p->Ue_lo, 128, Ueb,
            nullptr, p->uex, nullptr, N_HID, nullptr, 0,
            nullptr, nullptr, nullptr, nullptr, nullptr, 0, nullptr, 0, nullptr, nullptr);
    }
}

// ===================== prep kernels =====================
__global__ void init_state_kernel() {
    int i = blockIdx.x * 256 + threadIdx.x;
    bf16 z = __float2bfloat16(0.f);
    db.ce_f[i] = 0.f; db.cm_f[i] = 0.f; db.cd_f[i] = 0.f;
    // "step -1" parity buffers: he/ce/cd/hd in [1] (read at iter 0, rp=0... he[rp=0])
    db.he_hi[0][i] = z; db.he_lo[0][i] = z;
    db.ce_hi[0][i] = z; db.ce_lo[0][i] = z;
    db.hm_hi[0][i] = z; db.hm_lo[0][i] = z;   // hm(-1) read at iter1 via hm[wp=0]
    db.hd_hi[0][i] = z; db.hd_lo[0][i] = z;
    db.cd_hi[0][i] = z; db.cd_lo[0][i] = z;
}

__global__ void split_arr(const float* __restrict__ src, bf16* __restrict__ hi,
                          bf16* __restrict__ lo, int n) {
    int i = blockIdx.x * 256 + threadIdx.x;
    if (i >= n) return;
    splitf(src[i], hi[i], lo[i]);
}

__global__ void gates_prep(const float* __restrict__ Wih, int Ki,
                           const float* __restrict__ Whh,
                           const float* __restrict__ bih, const float* __restrict__ bhh,
                           bf16* __restrict__ Whi, bf16* __restrict__ Wlo,
                           float* __restrict__ br, int Kt)
{
    int idx = blockIdx.x * 256 + threadIdx.x;
    if (idx >= 1024 * Kt) return;
    int nrow = idx / Kt, k = idx - nrow * Kt;
    int h = nrow >> 2, g = nrow & 3;
    float v = (k < Ki) ? Wih[(size_t)(g * 256 + h) * Ki + k]
                       : Whh[(size_t)(g * 256 + h) * 256 + (k - Ki)];
    splitf(v, Whi[idx], Wlo[idx]);
    if (k == 0) br[nrow] = bih[g * 256 + h] + bhh[g * 256 + h];
}

__global__ void __launch_bounds__(256) transpose_split_kernel(const float* __restrict__ inp) {
    __shared__ float tile[32][33];
    const int b  = blockIdx.x;
    const int tx = threadIdx.x & 31, ty = threadIdx.x >> 5;
    const float* ib = inp + (size_t)b * (T_ENC * N_INP);
    for (int tt = 0; tt < 4; tt++)
        for (int jj = 0; jj < 4; jj++) {
            #pragma unroll
            for (int r = 0; r < 4; r++) {
                int t = tt * 32 + ty + r * 8, j = jj * 32 + tx;
                tile[ty + r * 8][tx] = ib[t * N_INP + j];
            }
            __syncthreads();
            #pragma unroll
            for (int r = 0; r < 4; r++) {
                int j = jj * 32 + ty + r * 8, t = tt * 32 + tx;
                bf16 hi, lo; splitf(tile[tx][ty + r * 8], hi, lo);
                size_t o = (size_t)b * (N_INP * T_ENC) + (size_t)j * T_ENC + t;
                db.inpT_hi[o] = hi; db.inpT_lo[o] = lo;
            }
            __syncthreads();
        }
}

// ===================== attention kernels =====================
__global__ void __launch_bounds__(256) attn_enc_kernel(
    const float* __restrict__ inp, const float* __restrict__ VeW,
    const float* __restrict__ VeB, int t)
{
    const int b = blockIdx.x;
    const int tid = threadIdx.x;
    const int lane = tid & 31;
    const int w = tid >> 5;

    __shared__ float sq[256], sv[256], ssc[128], sred[256];
    sq[tid] = db.q[(size_t)b * N_HID + tid];
    sv[tid] = VeW[tid];
    __syncthreads();

    const bf16* ub = db.uex + (size_t)b * (N_INP * N_HID);
    const float veb = VeB[0];

    for (int j = w; j < N_INP; j += 8) {
        const __nv_bfloat162* up = (const __nv_bfloat162*)(ub + (size_t)j * N_HID);
        float s = 0.f;
        #pragma unroll
        for (int i = 0; i < 4; i++) {
            __nv_bfloat162 u2 = up[lane + 32 * i];
            int k = 64 * i + 2 * lane;
            s += sv[k]     * tanhfast(sq[k]     + __low2float(u2));
            s += sv[k + 1] * tanhfast(sq[k + 1] + __high2float(u2));
        }
        #pragma unroll
        for (int o = 16; o > 0; o >>= 1) s += __shfl_xor_sync(0xffffffffu, s, o);
        if (lane == 0) ssc[j] = s + veb;
    }
    __syncthreads();

    float x = (tid < 128) ? ssc[tid] : -1e30f;
    sred[tid] = x; __syncthreads();
    #pragma unroll
    for (int o = 128; o > 0; o >>= 1) {
        if (tid < o) sred[tid] = fmaxf(sred[tid], sred[tid + o]);
        __syncthreads();
    }
    float mx = sred[0];
    __syncthreads();
    float e = (tid < 128) ? expf(x - mx) : 0.f;
    sred[tid] = e; __syncthreads();
    #pragma unroll
    for (int o = 128; o > 0; o >>= 1) {
        if (tid < o) sred[tid] += sred[tid + o];
        __syncthreads();
    }
    float inv = 1.0f / sred[0];
    if (tid < 128) {
        float xv = inp[((size_t)b * T_ENC + t) * N_INP + tid];
        bf16 hh, hl; splitf(xv * e * inv, hh, hl);
        db.xa_hi[(size_t)b * N_INP + tid] = hh;
        db.xa_lo[(size_t)b * N_INP + tid] = hl;
    }
}

__global__ void __launch_bounds__(256) attn_dec_kernel(
    const float* __restrict__ VdW, const float* __restrict__ VdB)
{
    const int b = blockIdx.x;
    const int tid = threadIdx.x;
    const int lane = tid & 31;
    const int w = tid >> 5;

    __shared__ float sq[256], sv[256], st[128];
    sq[tid] = db.q[(size_t)b * N_HID + tid];
    sv[tid] = VdW[tid];
    __syncthreads();

    const bf16* ubh = db.udmid_hi + (size_t)b * (T_ENC * N_HID);
    const bf16* ubl = db.udmid_lo + (size_t)b * (T_ENC * N_HID);
    const float vdb = VdB[0];

    for (int j = w; j < T_ENC; j += 8) {
        const __nv_bfloat162* uph = (const __nv_bfloat162*)(ubh + (size_t)j * N_HID);
        const __nv_bfloat162* upl = (const __nv_bfloat162*)(ubl + (size_t)j * N_HID);
        float s = 0.f;
        #pragma unroll
        for (int i = 0; i < 4; i++) {
            __nv_bfloat162 u2 = uph[lane + 32 * i];
            __nv_bfloat162 l2 = upl[lane + 32 * i];
            int k = 64 * i + 2 * lane;
            s += sv[k]     * tanhfast(sq[k]     + __low2float(u2)  + __low2float(l2));
            s += sv[k + 1] * tanhfast(sq[k + 1] + __high2float(u2) + __high2float(l2));
        }
        #pragma unroll
        for (int o = 16; o > 0; o >>= 1) s += __shfl_xor_sync(0xffffffffu, s, o);
        if (lane == 0) st[j] = s + vdb;
    }
    __syncthreads();

    const float* mb = db.mid + (size_t)b * (T_ENC * N_HID) + tid;
    float acc = 0.f;
    #pragma unroll 8
    for (int j = 0; j < T_ENC; j++)
        acc += st[j] * mb[(size_t)j * N_HID];
    bf16 hh, hl; splitf(acc, hh, hl);
    db.di_hi[(size_t)b * N_HID + tid] = hh;
    db.di_lo[(size_t)b * N_HID + tid] = hl;
}

// ===================== final regression output =====================
__global__ void __launch_bounds__(256) reg_kernel(
    const float* __restrict__ regW, const float* __restrict__ regB,
    float* __restrict__ out, int col)
{
    const int b = blockIdx.x;
    const int n = threadIdx.x;
    __shared__ float sr[256];
    sr[n] = regW[n] * db.hd_f[(size_t)b * N_HID + n];
    __syncthreads();
    #pragma unroll
    for (int o = 128; o > 0; o >>= 1) {
        if (n < o) sr[n] += sr[n + o];
        __syncthreads();
    }
    if (n == 0) out[(size_t)b * T_DEC + col] = sr[0] + regB[0];
}

// ===================== host launcher =====================
extern "C" void kernel_launch(void* const* d_in, const int* in_sizes, int n_in,
                              void* d_out, int out_size)
{
    (void)in_sizes; (void)n_in; (void)out_size;
    const float* inp  = (const float*)d_in[0];
    const float* UeW  = (const float*)d_in[2];
    const float* Ueb  = (const float*)d_in[3];
    const float* Ue2W = (const float*)d_in[4];
    const float* Ue2b = (const float*)d_in[5];
    const float* WeW  = (const float*)d_in[6];
    const float* Web  = (const float*)d_in[7];
    const float* VeW  = (const float*)d_in[8];
    const float* Veb  = (const float*)d_in[9];
    const float* UdW  = (const float*)d_in[10];
    const float* Udb  = (const float*)d_in[11];
    const float* WdW  = (const float*)d_in[12];
    const float* Wdb  = (const float*)d_in[13];
    const float* VdW  = (const float*)d_in[14];
    const float* Vdb  = (const float*)d_in[15];
    const float* eWih = (const float*)d_in[16];
    const float* eWhh = (const float*)d_in[17];
    const float* ebih = (const float*)d_in[18];
    const float* ebhh = (const float*)d_in[19];
    const float* mWih = (const float*)d_in[20];
    const float* mWhh = (const float*)d_in[21];
    const float* mbih = (const float*)d_in[22];
    const float* mbhh = (const float*)d_in[23];
    const float* dWih = (const float*)d_in[24];
    const float* dWhh = (const float*)d_in[25];
    const float* dbih = (const float*)d_in[26];
    const float* dbhh = (const float*)d_in[27];
    const float* regW = (const float*)d_in[28];
    const float* regb = (const float*)d_in[29];
    float* out = (float*)d_out;

    cudaFuncSetAttribute(mma_gemm,   cudaFuncAttributeMaxDynamicSharedMemorySize, SMEM_BYTES);
    cudaFuncSetAttribute(enc_combo,  cudaFuncAttributeMaxDynamicSharedMemorySize, SMEM_BYTES);
    cudaFuncSetAttribute(dec_combo,  cudaFuncAttributeMaxDynamicSharedMemorySize, SMEM_BYTES);
    cudaFuncSetAttribute(prol_combo, cudaFuncAttributeMaxDynamicSharedMemorySize, SMEM_BYTES);

    DB* p;
    cudaGetSymbolAddress((void**)&p, db);

    init_state_kernel<<<1024, 256>>>();

    split_arr<<<(B_SZ * T_ENC * N_INP + 255) / 256, 256>>>(inp, p->inp_hi, p->inp_lo, B_SZ * T_ENC * N_INP);
    split_arr<<<(256 * 512 + 255) / 256, 256>>>(WeW,  p->We_hi,  p->We_lo,  256 * 512);
    split_arr<<<(256 * 512 + 255) / 256, 256>>>(WdW,  p->Wd_hi,  p->Wd_lo,  256 * 512);
    split_arr<<<(256 * 128 + 255) / 256, 256>>>(Ue2W, p->Ue2_hi, p->Ue2_lo, 256 * 128);
    split_arr<<<(256 * 128 + 255) / 256, 256>>>(UeW,  p->Ue_hi,  p->Ue_lo,  256 * 128);
    split_arr<<<(256 * 256 + 255) / 256, 256>>>(UdW,  p->Ud_hi,  p->Ud_lo,  256 * 256);
    gates_prep<<<(1024 * 384 + 255) / 256, 256>>>(eWih, 128, eWhh, ebih, ebhh, p->Ge_hi, p->Ge_lo, p->be, 384);
    gates_prep<<<(1024 * 512 + 255) / 256, 256>>>(mWih, 256, mWhh, mbih, mbhh, p->Gm_hi, p->Gm_lo, p->bm, 512);
    gates_prep<<<(1024 * 512 + 255) / 256, 256>>>(dWih, 256, dWhh, dbih, dbhh, p->Gd_hi, p->Gd_lo, p->bd, 512);

    transpose_split_kernel<<<B_SZ, 256>>>(inp);

    // xi + uex in one launch
    prol_combo<<<8192, 256, SMEM_BYTES>>>(Ue2b, Ueb);

    // -------- encoder + mid recurrence (mid shifted by 1 into q's launch) ----
    for (int t = 0; t < T_ENC; t++) {
        int rp = t & 1, wp = rp ^ 1;
        enc_combo<<<160, 256, SMEM_BYTES>>>(t, Web);
        attn_enc_kernel<<<B_SZ, 256>>>(inp, VeW, Veb, t);
        // enc gates + cell (3-pass)
        mma_gemm<<<dim3(8, 16), 256, SMEM_BYTES>>>(
            2, 3, 384, 128,
            p->xa_hi, p->xa_lo, 128, p->he_hi[rp], p->he_lo[rp], 256,
            p->Ge_hi, p->Ge_lo, 384, p->be,
            nullptr, nullptr, nullptr, 0, nullptr, 0,
            p->ce_f, p->he_hi[wp], p->he_lo[wp],
            nullptr, nullptr, 0, nullptr, 0,
            p->ce_hi[wp], p->ce_lo[wp]);
    }
    // leftover mid(127): virtual iter 128 (rp=0, wp=1)
    mma_gemm<<<dim3(8, 16), 256, SMEM_BYTES>>>(
        2, 3, 512, 256,
        p->he_hi[0], p->he_lo[0], 256, p->hm_hi[1], p->hm_lo[1], 256,
        p->Gm_hi, p->Gm_lo, 512, p->bm,
        nullptr, nullptr, nullptr, 0, nullptr, 0,
        p->cm_f, p->hm_hi[0], p->hm_lo[0],
        p->mid_hi + (size_t)127 * N_HID, p->mid_lo + (size_t)127 * N_HID, (size_t)T_ENC * N_HID,
        p->mid + (size_t)127 * N_HID, (size_t)T_ENC * N_HID,
        nullptr, nullptr);

    // ud_mid = mid @ Ud^T + b  (3-pass, split hi/lo out)
    mma_gemm<<<dim3(2, 2048), 256, SMEM_BYTES>>>(
        3, 3, 256, 256,
        p->mid_hi, p->mid_lo, 256, nullptr, nullptr, 0,
        p->Ud_hi, p->Ud_lo, 256, Udb,
        nullptr, p->udmid_hi, p->udmid_lo, N_HID, nullptr, 0,
        nullptr, nullptr, nullptr, nullptr, nullptr, 0, nullptr, 0, nullptr, nullptr);

    // -------- decoder --------
    for (int s = 0; s < DEC_STEPS; s++) {
        int rp = s & 1, wp = rp ^ 1;
        dec_combo<<<1056, 256, SMEM_BYTES>>>(s, Wdb, regW, regb, out);
        attn_dec_kernel<<<B_SZ, 256>>>(VdW, Vdb);
        mma_gemm<<<dim3(8, 16), 256, SMEM_BYTES>>>(
            2, 3, 512, 256,
            p->di_hi, p->di_lo, 256, p->hd_hi[rp], p->hd_lo[rp], 256,
            p->Gd_hi, p->Gd_lo, 512, p->bd,
            nullptr, nullptr, nullptr, 0, nullptr, 0,
            p->cd_f, p->hd_hi[wp], p->hd_lo[wp],
            nullptr, nullptr, 0,
            p->hd_f, 256,
            p->cd_hi[wp], p->cd_lo[wp]);
    }
    reg_kernel<<<B_SZ, 256>>>(regW, regb, out, T_DEC - 1);
}